// round 12
// baseline (speedup 1.0000x reference)
#include <cuda_runtime.h>
#include <cuda_bf16.h>
#include <cuda_fp16.h>
#include <cstdint>
#include <math.h>

// ---------------- problem constants ----------------
#define TSTEPS 32
#define NBATCH 64
#define NPIX   64
#define ENCC   1536
#define EMBD   512
#define ADIM   512
#define HDIM   512
#define G4     2048     // 4*H
#define VOCAB  10000
#define VPAD   10048    // 157*64
#define MROWS  4096     // N*P
#define KINIT  98304    // P*ENC
#define NSPLIT 96       // init split-K

// ---------------- scratch (__device__ globals; no allocation) ----------------
__device__ __align__(16) __nv_bfloat16 d_feat_h[MROWS * ENCC];
__device__ __align__(16) __nv_bfloat16 d_feat_l[MROWS * ENCC];
__device__ __align__(16) __nv_bfloat16 d_Wih_h[G4 * G4];
__device__ __align__(16) __nv_bfloat16 d_Wih_l[G4 * G4];
__device__ __align__(16) __nv_bfloat16 d_afW_h[ADIM * ENCC];
__device__ __align__(16) __nv_bfloat16 d_afW_l[ADIM * ENCC];
__device__ __align__(16) __nv_bfloat16 d_fcW_h[VPAD * HDIM];
__device__ __align__(16) __nv_bfloat16 d_fcW_l[VPAD * HDIM];
__device__ __align__(16) __nv_bfloat16 d_embbf_h[TSTEPS * NBATCH * EMBD];
__device__ __align__(16) __nv_bfloat16 d_embbf_l[TSTEPS * NBATCH * EMBD];
__device__ __align__(16) __nv_bfloat16 d_houtbf_h[TSTEPS * NBATCH * HDIM];
__device__ __align__(16) __nv_bfloat16 d_houtbf_l[TSTEPS * NBATCH * HDIM];
// stacked small-GEMM weights: rows 0-511 attn_token_W, rows 512-2559 W_hh
__device__ __align__(16) __nv_bfloat16 d_sW_h[2560 * 512];
__device__ __align__(16) __nv_bfloat16 d_sW_l[2560 * 512];
// per-step h in bf16 hi/lo
__device__ __align__(16) __nv_bfloat16 d_hbf_h[NBATCH * HDIM];
__device__ __align__(16) __nv_bfloat16 d_hbf_l[NBATCH * HDIM];

__device__ __align__(16) __half d_attn_img[MROWS * ADIM];            // fp16, 4 MB
__device__ __align__(16) __half d_G[(size_t)NBATCH * G4 * NPIX];     // fp16, 16.7 MB
__device__ float d_pre[TSTEPS * NBATCH * G4];
__device__ float d_part[NSPLIT * 64 * 1024];       // init split-K partials (25MB)
__device__ float d_c[NBATCH * HDIM];
__device__ float d_P1[4 * NBATCH * ADIM];
__device__ float d_P3[4 * NBATCH * G4];
__device__ float d_logits[NBATCH * NPIX];

// intra-launch ordering counters (monotonic across the 32 step launches)
__device__ unsigned g_cP1, g_cP3, g_cSM;

// =====================================================================
// warp-MMA + cp.async helpers (sm_80+ PTX, no arch-feature gating)
// =====================================================================
__device__ __forceinline__ uint32_t smem_u32(const void* p) {
    uint32_t a;
    asm("{ .reg .u64 t; cvta.to.shared.u64 t, %1; cvt.u32.u64 %0, t; }" : "=r"(a) : "l"(p));
    return a;
}
__device__ __forceinline__ void ldsm_x4(uint32_t* r, uint32_t addr) {
    asm volatile("ldmatrix.sync.aligned.m8n8.x4.shared.b16 {%0,%1,%2,%3}, [%4];"
                 : "=r"(r[0]), "=r"(r[1]), "=r"(r[2]), "=r"(r[3]) : "r"(addr));
}
__device__ __forceinline__ void ldsm_x4_t(uint32_t* r, uint32_t addr) {
    asm volatile("ldmatrix.sync.aligned.m8n8.x4.trans.shared.b16 {%0,%1,%2,%3}, [%4];"
                 : "=r"(r[0]), "=r"(r[1]), "=r"(r[2]), "=r"(r[3]) : "r"(addr));
}
__device__ __forceinline__ void mma_bf16(float* c, const uint32_t* a, const uint32_t* b) {
    asm volatile(
        "mma.sync.aligned.m16n8k16.row.col.f32.bf16.bf16.f32 "
        "{%0,%1,%2,%3}, {%4,%5,%6,%7}, {%8,%9}, {%0,%1,%2,%3};"
        : "+f"(c[0]), "+f"(c[1]), "+f"(c[2]), "+f"(c[3])
        : "r"(a[0]), "r"(a[1]), "r"(a[2]), "r"(a[3]), "r"(b[0]), "r"(b[1]));
}
__device__ __forceinline__ void cp16(uint32_t dst, const void* src, bool pred) {
    int sz = pred ? 16 : 0;
    asm volatile("cp.async.cg.shared.global [%0], [%1], 16, %2;"
                 :: "r"(dst), "l"(src), "r"(sz) : "memory");
}
#define CP_COMMIT() asm volatile("cp.async.commit_group;" ::: "memory")
#define CP_WAIT1()  asm volatile("cp.async.wait_group 1;" ::: "memory")

// =====================================================================
// Fused fp32 -> bf16 hi/lo conversion (6 segments).
// =====================================================================
__global__ void cvt_all(const float* __restrict__ feat,
                        const float* __restrict__ Wih,
                        const float* __restrict__ afW,
                        const float* __restrict__ fcW,
                        const float* __restrict__ tokW,
                        const float* __restrict__ Whh)
{
    int b = blockIdx.x;
    const float* src;
    __nv_bfloat16 *dh, *dl;
    int n_src, lb;
    if (b < 6144)       { src = feat; dh = d_feat_h; dl = d_feat_l; n_src = MROWS * ENCC; lb = b; }
    else if (b < 10240) { src = Wih;  dh = d_Wih_h;  dl = d_Wih_l;  n_src = G4 * G4;      lb = b - 6144; }
    else if (b < 11008) { src = afW;  dh = d_afW_h;  dl = d_afW_l;  n_src = ADIM * ENCC;  lb = b - 10240; }
    else if (b < 16032) { src = fcW;  dh = d_fcW_h;  dl = d_fcW_l;  n_src = VOCAB * HDIM; lb = b - 11008; }
    else if (b < 16288) { src = tokW; dh = d_sW_h;   dl = d_sW_l;   n_src = 512 * 512;    lb = b - 16032; }
    else                { src = Whh;  dh = d_sW_h + 262144; dl = d_sW_l + 262144;
                          n_src = 2048 * 512; lb = b - 16288; }
    int i = (lb * 256 + threadIdx.x) * 4;
    float4 v = make_float4(0.f, 0.f, 0.f, 0.f);
    if (i < n_src) v = *(const float4*)&src[i];
    float a[4] = {v.x, v.y, v.z, v.w};
    __nv_bfloat16 h[4], l[4];
#pragma unroll
    for (int j = 0; j < 4; j++) {
        h[j] = __float2bfloat16(a[j]);
        l[j] = __float2bfloat16(a[j] - __bfloat162float(h[j]));
    }
    *(__nv_bfloat162*)&dh[i]     = __halves2bfloat162(h[0], h[1]);
    *(__nv_bfloat162*)&dh[i + 2] = __halves2bfloat162(h[2], h[3]);
    *(__nv_bfloat162*)&dl[i]     = __halves2bfloat162(l[0], l[1]);
    *(__nv_bfloat162*)&dl[i + 2] = __halves2bfloat162(l[2], l[3]);
}

// embedding gather straight into bf16 hi/lo [t*64+n][e]
__global__ void emb_gather_bf(const int* __restrict__ cap,
                              const float* __restrict__ EW,
                              __nv_bfloat16* __restrict__ dh,
                              __nv_bfloat16* __restrict__ dl)
{
    int m = blockIdx.x;                 // t*64+n
    int n = m & 63, t = m >> 6;
    int tok = cap[n * TSTEPS + t];
    int i = threadIdx.x * 4;            // 128 thr * 4 = 512
    float4 v = *(const float4*)&EW[(size_t)tok * EMBD + i];
    float a[4] = {v.x, v.y, v.z, v.w};
    __nv_bfloat16 h[4], l[4];
#pragma unroll
    for (int j = 0; j < 4; j++) {
        h[j] = __float2bfloat16(a[j]);
        l[j] = __float2bfloat16(a[j] - __bfloat162float(h[j]));
    }
    size_t o = (size_t)m * EMBD + i;
    *(__nv_bfloat162*)&dh[o]     = __halves2bfloat162(h[0], h[1]);
    *(__nv_bfloat162*)&dh[o + 2] = __halves2bfloat162(h[2], h[3]);
    *(__nv_bfloat162*)&dl[o]     = __halves2bfloat162(l[0], l[1]);
    *(__nv_bfloat162*)&dl[o + 2] = __halves2bfloat162(l[2], l[3]);
}

// =====================================================================
// Warp-MMA NT GEMM, bf16 hi/lo split, fp32 accumulate, cp.async 2-stage.
// mode 0: fp32 C[m*ldc+n] (+bias)
// mode 3: merged — blockIdx.x<8: attn_img fp16 (+bias); else G fp16 layout
// =====================================================================
#define ASTR 72
#define AH_OFF 0
#define AL_OFF 18432
#define BH_OFF 36864
#define BL_OFF 46080
#define STAGE_BYTES 55296
#define MMA_SMEM_BYTES (2 * STAGE_BYTES)

__global__ void __launch_bounds__(256) mma_nt(
    const __nv_bfloat16* __restrict__ Ah, const __nv_bfloat16* __restrict__ Al,
    int lda, int Mvalid,
    const __nv_bfloat16* __restrict__ Bh, const __nv_bfloat16* __restrict__ Bl,
    int ldb,
    float* __restrict__ C, int Nvalid, int ldc,
    int chunks, const float* __restrict__ bias, int mode)
{
    extern __shared__ char smem[];
    const uint32_t sb = smem_u32(smem);
    const int tid = threadIdx.x, lane = tid & 31, wid = tid >> 5;
    const int wm = wid >> 1, wn = wid & 1;
    const int m0 = blockIdx.y * 128;

    const __nv_bfloat16* bH = Bh;
    const __nv_bfloat16* bL = Bl;
    const float* bptr = bias;
    int n0 = blockIdx.x * 64;
    int mode_eff = mode;
    if (mode == 3) {
        if (blockIdx.x < 8) {
            mode_eff = 4;
        } else {
            bH = d_Wih_h; bL = d_Wih_l; ldb = G4;
            bptr = nullptr;
            n0 = (blockIdx.x - 8) * 64;
            mode_eff = 1;
        }
    }

    float acc[2][4][4];
#pragma unroll
    for (int i = 0; i < 2; i++)
#pragma unroll
        for (int j = 0; j < 4; j++)
#pragma unroll
            for (int q = 0; q < 4; q++) acc[i][j][q] = 0.f;

    const uint32_t a_row = wm * 32 + (lane & 15);
    const uint32_t a_k   = ((lane >> 4) & 1) * 8;
    const uint32_t b_row = wn * 32 + (lane & 7) + ((lane >> 4) & 1) * 8;
    const uint32_t b_k   = ((lane >> 3) & 1) * 8;

    auto load_stage = [&](int ic, int st) {
        const uint32_t stb = sb + st * STAGE_BYTES;
        const long long kc = (long long)ic * 64;
#pragma unroll
        for (int it = 0; it < 4; it++) {
            int idx = it * 256 + tid;
            int row = idx >> 3, k8 = (idx & 7) * 8;
            int m = m0 + row;
            bool p = (m < Mvalid);
            int mc = p ? m : (Mvalid - 1);
            uint32_t off = (row * ASTR + k8) * 2;
            cp16(stb + AH_OFF + off, &Ah[(size_t)mc * lda + kc + k8], p);
            cp16(stb + AL_OFF + off, &Al[(size_t)mc * lda + kc + k8], p);
        }
#pragma unroll
        for (int it = 0; it < 2; it++) {
            int idx = it * 256 + tid;
            int row = idx >> 3, k8 = (idx & 7) * 8;
            uint32_t off = (row * ASTR + k8) * 2;
            cp16(stb + BH_OFF + off, &bH[(size_t)(n0 + row) * ldb + kc + k8], true);
            cp16(stb + BL_OFF + off, &bL[(size_t)(n0 + row) * ldb + kc + k8], true);
        }
    };

    load_stage(0, 0);
    CP_COMMIT();

    for (int ic = 0; ic < chunks; ic++) {
        const int s = ic & 1;
        if (ic + 1 < chunks) load_stage(ic + 1, s ^ 1);
        CP_COMMIT();
        CP_WAIT1();
        __syncthreads();

        const uint32_t stb = sb + s * STAGE_BYTES;
#pragma unroll
        for (int ks = 0; ks < 4; ks++) {
            const uint32_t k16 = ks * 16;
            uint32_t ahf[2][4], alf[2][4], bhf[2][4], blf[2][4];
#pragma unroll
            for (int mt = 0; mt < 2; mt++) {
                uint32_t off = ((a_row + mt * 16) * ASTR + k16 + a_k) * 2;
                ldsm_x4(ahf[mt], stb + AH_OFF + off);
                ldsm_x4(alf[mt], stb + AL_OFF + off);
            }
#pragma unroll
            for (int np = 0; np < 2; np++) {
                uint32_t off = ((b_row + np * 16) * ASTR + k16 + b_k) * 2;
                ldsm_x4(bhf[np], stb + BH_OFF + off);
                ldsm_x4(blf[np], stb + BL_OFF + off);
            }
#pragma unroll
            for (int mt = 0; mt < 2; mt++)
#pragma unroll
                for (int np = 0; np < 2; np++) {
                    mma_bf16(acc[mt][np * 2 + 0], ahf[mt], &bhf[np][0]);
                    mma_bf16(acc[mt][np * 2 + 1], ahf[mt], &bhf[np][2]);
                    mma_bf16(acc[mt][np * 2 + 0], ahf[mt], &blf[np][0]);
                    mma_bf16(acc[mt][np * 2 + 1], ahf[mt], &blf[np][2]);
                    mma_bf16(acc[mt][np * 2 + 0], alf[mt], &bhf[np][0]);
                    mma_bf16(acc[mt][np * 2 + 1], alf[mt], &bhf[np][2]);
                }
        }
        __syncthreads();
    }

    const int g = lane >> 2, tg = lane & 3;
#pragma unroll
    for (int mt = 0; mt < 2; mt++) {
#pragma unroll
        for (int nt = 0; nt < 4; nt++) {
            int r0 = m0 + wm * 32 + mt * 16 + g;
            int c0 = n0 + wn * 32 + nt * 8 + tg * 2;
#pragma unroll
            for (int q = 0; q < 4; q++) {
                int m = r0 + (q >> 1) * 8;
                int n = c0 + (q & 1);
                if (m >= Mvalid) continue;
                float v = acc[mt][nt][q];
                if (mode_eff == 1) {
                    int nb = m >> 6, p = m & 63;
                    d_G[((size_t)nb * 2048 + n) * 64 + p] = __float2half(v);
                } else if (mode_eff == 4) {
                    d_attn_img[(size_t)m * ADIM + n] = __float2half(v + bptr[n]);
                } else {
                    if (n < Nvalid) {
                        if (bptr) v += bptr[n];
                        C[(size_t)m * ldc + n] = v;
                    }
                }
            }
        }
    }
}

// =====================================================================
// Fused init GEMM: h0|c0 = F(64x98304) @ [Wh|Wc]; split-K 96.
// =====================================================================
#define IBSTR 136
#define IA_H 0
#define IA_L 9216
#define IB_H 18432
#define IB_L 35840
#define INIT_SMEM_BYTES 53248

__global__ void __launch_bounds__(256) init_mma(
    const float* __restrict__ Wh, const float* __restrict__ Wc,
    float* __restrict__ P)
{
    extern __shared__ char smem[];
    const uint32_t sb = smem_u32(smem);
    __nv_bfloat16* Bsh = (__nv_bfloat16*)(smem + IB_H);
    __nv_bfloat16* Bsl = (__nv_bfloat16*)(smem + IB_L);
    const int tid = threadIdx.x, lane = tid & 31, wid = tid >> 5;
    const int wm = wid >> 2, wn = wid & 3;
    const int bx = blockIdx.x;
    const float* __restrict__ W = (bx < 4) ? Wh : Wc;
    const int n0g = (bx & 3) * 128;
    const int outc0 = bx * 128;
    const size_t k0 = (size_t)blockIdx.y * 1024;

    float acc[2][4][4];
#pragma unroll
    for (int i = 0; i < 2; i++)
#pragma unroll
        for (int j = 0; j < 4; j++)
#pragma unroll
            for (int q = 0; q < 4; q++) acc[i][j][q] = 0.f;

    const uint32_t a_row = wm * 32 + (lane & 15);
    const uint32_t a_k   = ((lane >> 4) & 1) * 8;
    const uint32_t bt_k = ((lane >> 3) & 1) * 8 + (lane & 7);
    const uint32_t bt_n = ((lane >> 4) & 1) * 8;

    for (int ic = 0; ic < 16; ic++) {
        const size_t kg = k0 + ic * 64;
#pragma unroll
        for (int it = 0; it < 2; it++) {
            int idx = it * 256 + tid;
            int row = idx >> 3, k8 = (idx & 7) * 8;
            uint32_t off = (row * ASTR + k8) * 2;
            *(uint4*)(smem + IA_H + off) = *(const uint4*)&d_feat_h[(size_t)row * KINIT + kg + k8];
            *(uint4*)(smem + IA_L + off) = *(const uint4*)&d_feat_l[(size_t)row * KINIT + kg + k8];
        }
#pragma unroll
        for (int it = 0; it < 8; it++) {
            int idx = it * 256 + tid;
            int kk = idx >> 5, nn = (idx & 31) * 4;
            float4 v = *(const float4*)&W[(kg + kk) * 512 + n0g + nn];
            float a[4] = {v.x, v.y, v.z, v.w};
            __nv_bfloat16 h[4], l[4];
#pragma unroll
            for (int j = 0; j < 4; j++) {
                h[j] = __float2bfloat16(a[j]);
                l[j] = __float2bfloat16(a[j] - __bfloat162float(h[j]));
            }
            int o = kk * IBSTR + nn;
            *(__nv_bfloat162*)&Bsh[o]     = __halves2bfloat162(h[0], h[1]);
            *(__nv_bfloat162*)&Bsh[o + 2] = __halves2bfloat162(h[2], h[3]);
            *(__nv_bfloat162*)&Bsl[o]     = __halves2bfloat162(l[0], l[1]);
            *(__nv_bfloat162*)&Bsl[o + 2] = __halves2bfloat162(l[2], l[3]);
        }
        __syncthreads();

#pragma unroll
        for (int ks = 0; ks < 4; ks++) {
            const uint32_t k16 = ks * 16;
            uint32_t ahf[2][4], alf[2][4];
#pragma unroll
            for (int mt = 0; mt < 2; mt++) {
                uint32_t off = ((a_row + mt * 16) * ASTR + k16 + a_k) * 2;
                ldsm_x4(ahf[mt], sb + IA_H + off);
                ldsm_x4(alf[mt], sb + IA_L + off);
            }
#pragma unroll
            for (int ng = 0; ng < 2; ng++) {
                uint32_t bhf[4], blf[4];
                uint32_t off = ((k16 + bt_k) * IBSTR + wn * 32 + ng * 16 + bt_n) * 2;
                ldsm_x4_t(bhf, sb + IB_H + off);
                ldsm_x4_t(blf, sb + IB_L + off);
#pragma unroll
                for (int mt = 0; mt < 2; mt++) {
                    mma_bf16(acc[mt][ng * 2 + 0], ahf[mt], &bhf[0]);
                    mma_bf16(acc[mt][ng * 2 + 1], ahf[mt], &bhf[2]);
                    mma_bf16(acc[mt][ng * 2 + 0], ahf[mt], &blf[0]);
                    mma_bf16(acc[mt][ng * 2 + 1], ahf[mt], &blf[2]);
                    mma_bf16(acc[mt][ng * 2 + 0], alf[mt], &bhf[0]);
                    mma_bf16(acc[mt][ng * 2 + 1], alf[mt], &bhf[2]);
                }
            }
        }
        __syncthreads();
    }

    const int g = lane >> 2, tg = lane & 3;
    const int zb = blockIdx.y * 64;
#pragma unroll
    for (int mt = 0; mt < 2; mt++)
#pragma unroll
        for (int nt = 0; nt < 4; nt++) {
            int r0 = wm * 32 + mt * 16 + g;
            int c0 = outc0 + wn * 32 + nt * 8 + tg * 2;
#pragma unroll
            for (int q = 0; q < 4; q++) {
                int m = r0 + (q >> 1) * 8;
                int n = c0 + (q & 1);
                P[(size_t)(zb + m) * 1024 + n] = acc[mt][nt][q];
            }
        }
}

// deterministic reduce of NSPLIT split-K partials -> h0 (bf16 hi/lo), c0
__global__ void reduce_init(const float* __restrict__ P,
                            float* __restrict__ c)
{
    int r = blockIdx.x * 256 + threadIdx.x;   // 65536
    float s = 0.f;
#pragma unroll
    for (int j = 0; j < NSPLIT; j++) s += P[(size_t)j * 65536 + r];
    int m = r >> 10, col = r & 1023;
    if (col < 512) {
        __nv_bfloat16 hi = __float2bfloat16(s);
        d_hbf_h[m * 512 + col] = hi;
        d_hbf_l[m * 512 + col] = __float2bfloat16(s - __bfloat162float(hi));
    } else {
        c[m * 512 + col - 512] = s;
    }
}

// reset ordering counters (once per replay, before the loop)
__global__ void reset_ctr() { g_cP1 = 0u; g_cP3 = 0u; g_cSM = 0u; }

// =====================================================================
// FUSED STEP KERNEL: one launch per timestep. grid 736 x 256 threads.
//  blocks   0-159 : small GEMM units (h @ [tokW;W_hh], HMMA, split-K 4)
//  blocks 160-223 : attn_h reduce + scores + softmax  (spin on cP1)
//  blocks 224-735 : gates + LSTM                      (spin on cSM, cP3)
// Counters are monotonic: targets (t+1)*{32,128,64}. All phase widths
// preserved; math identical to R11 kernels.
// =====================================================================
#define SSTR 136
#define S_AH 0
#define S_AL 17408
#define S_BH 34816
#define S_BL 52224
#define STEP_SMEM 69632

__device__ __forceinline__ void spin_ge(volatile unsigned* p, unsigned target) {
    while (*p < target) { __nanosleep(64); }
}

__global__ void __launch_bounds__(256) step_fused(
    const float* __restrict__ tb,
    const float* __restrict__ wfull,
    const float* __restrict__ b_ih,
    const float* __restrict__ b_hh,
    const float* __restrict__ pre_t,
    int t)
{
    extern __shared__ char smem[];
    const uint32_t sb = smem_u32(smem);
    const int tid = threadIdx.x, lane = tid & 31, wid = tid >> 5;
    const unsigned cta = blockIdx.x;
    const unsigned tgt = (unsigned)(t + 1);

    if (cta < 160) {
        // ---------------- phase A: HMMA GEMM unit ----------------
        const int cb = cta >> 2, ks = cta & 3;
        const int k0 = ks * 128;
        float* __restrict__ P;
        int Ncols, cbl;
        if (cb < 8) { P = d_P1; Ncols = 512;  cbl = cb; }
        else        { P = d_P3; Ncols = 2048; cbl = cb - 8; }

#pragma unroll
        for (int it = 0; it < 4; it++) {           // 1024 uint4 / 256 thr
            int idx = it * 256 + tid;
            int row = idx >> 4, c8 = (idx & 15) * 8;
            uint32_t off = (row * SSTR + c8) * 2;
            *(uint4*)(smem + S_AH + off) = *(const uint4*)&d_hbf_h[row * 512 + k0 + c8];
            *(uint4*)(smem + S_AL + off) = *(const uint4*)&d_hbf_l[row * 512 + k0 + c8];
            *(uint4*)(smem + S_BH + off) = *(const uint4*)&d_sW_h[(size_t)(cb * 64 + row) * 512 + k0 + c8];
            *(uint4*)(smem + S_BL + off) = *(const uint4*)&d_sW_l[(size_t)(cb * 64 + row) * 512 + k0 + c8];
        }
        __syncthreads();

        if (wid < 4) {
            const int wm = wid >> 1, wn = wid & 1;
            float acc[2][4][4];
#pragma unroll
            for (int i = 0; i < 2; i++)
#pragma unroll
                for (int j = 0; j < 4; j++)
#pragma unroll
                    for (int q = 0; q < 4; q++) acc[i][j][q] = 0.f;

            const uint32_t a_row = wm * 32 + (lane & 15);
            const uint32_t a_k   = ((lane >> 4) & 1) * 8;
            const uint32_t b_row = wn * 32 + (lane & 7) + ((lane >> 4) & 1) * 8;
            const uint32_t b_k   = ((lane >> 3) & 1) * 8;

#pragma unroll
            for (int k16i = 0; k16i < 8; k16i++) {
                const uint32_t k16 = k16i * 16;
                uint32_t ahf[2][4], alf[2][4], bhf[2][4], blf[2][4];
#pragma unroll
                for (int mt = 0; mt < 2; mt++) {
                    uint32_t off = ((a_row + mt * 16) * SSTR + k16 + a_k) * 2;
                    ldsm_x4(ahf[mt], sb + S_AH + off);
                    ldsm_x4(alf[mt], sb + S_AL + off);
                }
#pragma unroll
                for (int np = 0; np < 2; np++) {
                    uint32_t off = ((b_row + np * 16) * SSTR + k16 + b_k) * 2;
                    ldsm_x4(bhf[np], sb + S_BH + off);
                    ldsm_x4(blf[np], sb + S_BL + off);
                }
#pragma unroll
                for (int mt = 0; mt < 2; mt++)
#pragma unroll
                    for (int np = 0; np < 2; np++) {
                        mma_bf16(acc[mt][np * 2 + 0], ahf[mt], &bhf[np][0]);
                        mma_bf16(acc[mt][np * 2 + 1], ahf[mt], &bhf[np][2]);
                        mma_bf16(acc[mt][np * 2 + 0], ahf[mt], &blf[np][0]);
                        mma_bf16(acc[mt][np * 2 + 1], ahf[mt], &blf[np][2]);
                        mma_bf16(acc[mt][np * 2 + 0], alf[mt], &bhf[np][0]);
                        mma_bf16(acc[mt][np * 2 + 1], alf[mt], &bhf[np][2]);
                    }
            }

            const int g = lane >> 2, tg = lane & 3;
#pragma unroll
            for (int mt = 0; mt < 2; mt++)
#pragma unroll
                for (int nt = 0; nt < 4; nt++) {
                    int r0 = wm * 32 + mt * 16 + g;
                    int c0 = cbl * 64 + wn * 32 + nt * 8 + tg * 2;
#pragma unroll
                    for (int q = 0; q < 4; q++) {
                        int m = r0 + (q >> 1) * 8;
                        int n = c0 + (q & 1);
                        P[(size_t)(ks * 64 + m) * Ncols + n] = acc[mt][nt][q];
                    }
                }
        }
        __threadfence();
        __syncthreads();
        if (tid == 0) atomicAdd((cb < 8) ? &g_cP1 : &g_cP3, 1u);

    } else if (cta < 224) {
        // ---------------- phase B: softmax ----------------
        const int n = cta - 160;
        float* ah = (float*)smem;        // 512
        float* wf = ah + 512;            // 512
        float* sc = wf + 512;            // 64

        if (tid == 0) spin_ge(&g_cP1, tgt * 32u);
        __syncthreads();

#pragma unroll
        for (int half = 0; half < 2; half++) {
            int a = half * 256 + tid;
            float v = tb[a];
#pragma unroll
            for (int s = 0; s < 4; s++)
                v += __ldcg(&d_P1[(size_t)(s * 64 + n) * 512 + a]);
            ah[a] = v;
            wf[a] = wfull[a];
        }
        __syncthreads();

        const int warp = tid >> 5;       // 8 warps
        for (int p = warp; p < 64; p += 8) {
            const __half* img = &d_attn_img[(size_t)(n * 64 + p) * 512];
            float s = 0.f;
#pragma unroll
            for (int a = lane; a < 512; a += 32) {
                float e = ah[a] + __half2float(img[a]);
                if (e > 0.f) s += e * wf[a];
            }
#pragma unroll
            for (int o = 16; o > 0; o >>= 1) s += __shfl_xor_sync(0xFFFFFFFFu, s, o);
            if (lane == 0) sc[p] = s;
        }
        __syncthreads();
        if (tid < 32) {
            float s0 = sc[tid], s1 = sc[tid + 32];
            float mx = fmaxf(s0, s1);
#pragma unroll
            for (int o = 16; o > 0; o >>= 1) mx = fmaxf(mx, __shfl_xor_sync(0xFFFFFFFFu, mx, o));
            float e0 = expf(s0 - mx), e1 = expf(s1 - mx);
            float sum = e0 + e1;
#pragma unroll
            for (int o = 16; o > 0; o >>= 1) sum += __shfl_xor_sync(0xFFFFFFFFu, sum, o);
            float inv = 1.f / sum;
            d_logits[n * 64 + tid]      = e0 * inv;
            d_logits[n * 64 + tid + 32] = e1 * inv;
        }
        __threadfence();
        __syncthreads();
        if (tid == 0) atomicAdd(&g_cSM, 1u);

    } else {
        // ---------------- phase C: gates + LSTM ----------------
        const int idx = cta - 224;
        const int n = idx >> 3, hc = idx & 7;
        float* lg = (float*)smem;        // 64
        float* sg = lg + 64;             // [4][64]

        if (tid == 0) {
            spin_ge(&g_cP3, tgt * 128u);
            spin_ge(&g_cSM, tgt * 64u);
        }
        __syncthreads();

        if (tid < 64) lg[tid] = __ldcg(&d_logits[n * 64 + tid]);
        __syncthreads();

        const int q = tid >> 6, hl = tid & 63;
        const int j = q * 512 + hc * 64 + hl;
        float acc = b_ih[j] + b_hh[j] + pre_t[n * 2048 + j];
#pragma unroll
        for (int s = 0; s < 4; s++)
            acc += __ldcg(&d_P3[(size_t)(s * 64 + n) * 2048 + j]);
        const uint4* g4 = (const uint4*)&d_G[((size_t)n * 2048 + j) * 64];
#pragma unroll
        for (int pi = 0; pi < 8; pi++) {
            uint4 u = g4[pi];
            __half2 h0 = *(__half2*)&u.x, h1 = *(__half2*)&u.y;
            __half2 h2 = *(__half2*)&u.z, h3 = *(__half2*)&u.w;
            float2 f0 = __half22float2(h0), f1 = __half22float2(h1);
            float2 f2 = __half22float2(h2), f3 = __half22float2(h3);
            const float* w = &lg[pi * 8];
            acc += w[0] * f0.x + w[1] * f0.y + w[2] * f1.x + w[3] * f1.y
                 + w[4] * f2.x + w[5] * f2.y + w[6] * f3.x + w[7] * f3.y;
        }
        sg[q * 64 + hl] = acc;
        __syncthreads();

        if (tid < 64) {
            int hidx = hc * 64 + tid;
            float ig = sg[0 * 64 + tid], fg = sg[1 * 64 + tid];
            float gg = sg[2 * 64 + tid], og = sg[3 * 64 + tid];
            float si = 1.f / (1.f + expf(-ig));
            float sf = 1.f / (1.f + expf(-fg));
            float so = 1.f / (1.f + expf(-og));
            float cn = sf * d_c[n * 512 + hidx] + si * tanhf(gg);
            float hn = so * tanhf(cn);
            d_c[n * 512 + hidx] = cn;
            __nv_bfloat16 hi = __float2bfloat16(hn);
            __nv_bfloat16 lo = __float2bfloat16(hn - __bfloat162float(hi));
            d_hbf_h[n * 512 + hidx] = hi;
            d_hbf_l[n * 512 + hidx] = lo;
            size_t o = ((size_t)n * TSTEPS + t) * 512 + hidx;
            d_houtbf_h[o] = hi;
            d_houtbf_l[o] = lo;
        }
    }
}

// =====================================================================
// Host side
// =====================================================================
template <typename Tp>
static void* symaddr(Tp& ref)
{
    void* p = nullptr;
    cudaGetSymbolAddress(&p, ref);
    return p;
}

extern "C" void kernel_launch(void* const* d_in, const int* in_sizes, int n_in,
                              void* d_out, int out_size)
{
    const float* features     = (const float*)d_in[0];
    const int*   captions     = (const int*)  d_in[1];
    const float* embd_W       = (const float*)d_in[2];
    const float* attn_token_W = (const float*)d_in[3];
    const float* attn_token_b = (const float*)d_in[4];
    const float* attn_feat_W  = (const float*)d_in[5];
    const float* attn_feat_b  = (const float*)d_in[6];
    const float* attn_full_W  = (const float*)d_in[7];
    // d_in[8] attn_full_b: softmax-invariant constant -> skipped
    const float* W_ih         = (const float*)d_in[9];
    const float* b_ih         = (const float*)d_in[10];
    const float* W_hh         = (const float*)d_in[11];
    const float* b_hh         = (const float*)d_in[12];
    const float* fc_W         = (const float*)d_in[13];
    const float* fc_b         = (const float*)d_in[14];
    const float* init_Wh      = (const float*)d_in[15];
    const float* init_Wc      = (const float*)d_in[16];
    float* out = (float*)d_out;

    __nv_bfloat16* p_feat_h = (__nv_bfloat16*)symaddr(d_feat_h);
    __nv_bfloat16* p_feat_l = (__nv_bfloat16*)symaddr(d_feat_l);
    __nv_bfloat16* p_Wih_h  = (__nv_bfloat16*)symaddr(d_Wih_h);
    __nv_bfloat16* p_Wih_l  = (__nv_bfloat16*)symaddr(d_Wih_l);
    __nv_bfloat16* p_afW_h  = (__nv_bfloat16*)symaddr(d_afW_h);
    __nv_bfloat16* p_afW_l  = (__nv_bfloat16*)symaddr(d_afW_l);
    __nv_bfloat16* p_fcW_h  = (__nv_bfloat16*)symaddr(d_fcW_h);
    __nv_bfloat16* p_fcW_l  = (__nv_bfloat16*)symaddr(d_fcW_l);
    __nv_bfloat16* p_emb_h  = (__nv_bfloat16*)symaddr(d_embbf_h);
    __nv_bfloat16* p_emb_l  = (__nv_bfloat16*)symaddr(d_embbf_l);
    __nv_bfloat16* p_hbf_h  = (__nv_bfloat16*)symaddr(d_houtbf_h);
    __nv_bfloat16* p_hbf_l  = (__nv_bfloat16*)symaddr(d_houtbf_l);

    float* p_pre  = (float*)symaddr(d_pre);
    float* p_part = (float*)symaddr(d_part);
    float* p_c    = (float*)symaddr(d_c);

    // opt-in to >48KB dynamic smem (idempotent)
    cudaFuncAttributes fa;
    cudaFuncGetAttributes(&fa, mma_nt);
    if (fa.maxDynamicSharedSizeBytes < MMA_SMEM_BYTES)
        cudaFuncSetAttribute(mma_nt, cudaFuncAttributeMaxDynamicSharedMemorySize,
                             MMA_SMEM_BYTES);
    cudaFuncGetAttributes(&fa, init_mma);
    if (fa.maxDynamicSharedSizeBytes < INIT_SMEM_BYTES)
        cudaFuncSetAttribute(init_mma, cudaFuncAttributeMaxDynamicSharedMemorySize,
                             INIT_SMEM_BYTES);
    cudaFuncGetAttributes(&fa, step_fused);
    if (fa.maxDynamicSharedSizeBytes < STEP_SMEM)
        cudaFuncSetAttribute(step_fused, cudaFuncAttributeMaxDynamicSharedMemorySize,
                             STEP_SMEM);

    // side stream + events for prologue fork
    static cudaStream_t s2 = nullptr;
    static cudaEvent_t evA = nullptr, evB = nullptr;
    if (!s2) {
        cudaStreamCreateWithFlags(&s2, cudaStreamNonBlocking);
        cudaEventCreateWithFlags(&evA, cudaEventDisableTiming);
        cudaEventCreateWithFlags(&evB, cudaEventDisableTiming);
    }

    // ---- conversions (stream 0) ----
    cvt_all<<<17312, 256>>>(features, W_ih, attn_feat_W, fc_W,
                            attn_token_W, W_hh);
    cudaEventRecord(evA, 0);

    // ---- fork: init GEMM chain on s2 ----
    cudaStreamWaitEvent(s2, evA, 0);
    init_mma<<<dim3(8, NSPLIT), 256, INIT_SMEM_BYTES, s2>>>(init_Wh, init_Wc, p_part);
    reduce_init<<<256, 256, 0, s2>>>(p_part, p_c);
    cudaEventRecord(evB, s2);

    // ---- stream 0: remaining prologue ----
    emb_gather_bf<<<TSTEPS * NBATCH, 128>>>(captions, embd_W, p_emb_h, p_emb_l);
    reset_ctr<<<1, 1>>>();
    // pre_emb = emb @ W_ih[:,1536:]^T  (2048 x 2048, K=512)
    mma_nt<<<dim3(32, 16, 1), 256, MMA_SMEM_BYTES>>>(
        p_emb_h, p_emb_l, EMBD, TSTEPS * NBATCH, p_Wih_h + 1536, p_Wih_l + 1536, G4,
        p_pre, G4, G4, 8, nullptr, 0);
    // merged: attn_img (fp16) + G (fp16)
    mma_nt<<<dim3(40, 32, 1), 256, MMA_SMEM_BYTES>>>(
        p_feat_h, p_feat_l, ENCC, MROWS, p_afW_h, p_afW_l, ENCC,
        nullptr, ADIM, ADIM, 24, attn_feat_b, 3);

    // ---- join: h0/c0 ready before the recurrence ----
    cudaStreamWaitEvent((cudaStream_t)0, evB, 0);

    // ---- sequential recurrence: ONE launch per step ----
    for (int t = 0; t < TSTEPS; ++t) {
        step_fused<<<736, 256, STEP_SMEM>>>(
            attn_token_b, attn_full_W, b_ih, b_hh,
            p_pre + (size_t)t * NBATCH * G4, t);
    }

    // ---- epilogue: FC over all timesteps ----
    mma_nt<<<dim3(157, 16, 1), 256, MMA_SMEM_BYTES>>>(
        p_hbf_h, p_hbf_l, HDIM, TSTEPS * NBATCH, p_fcW_h, p_fcW_l, HDIM,
        out, VOCAB, VOCAB, 8, fc_b, 0);
}

// round 13
// speedup vs baseline: 1.1156x; 1.1156x over previous
#include <cuda_runtime.h>
#include <cuda_bf16.h>
#include <cuda_fp16.h>
#include <cstdint>
#include <math.h>

// ---------------- problem constants ----------------
#define TSTEPS 32
#define NBATCH 64
#define NPIX   64
#define ENCC   1536
#define EMBD   512
#define ADIM   512
#define HDIM   512
#define G4     2048     // 4*H
#define VOCAB  10000
#define VPAD   10048    // 157*64
#define MROWS  4096     // N*P
#define KINIT  98304    // P*ENC
#define NSPLIT 96       // init split-K

// ---------------- scratch (__device__ globals; no allocation) ----------------
__device__ __align__(16) __nv_bfloat16 d_feat_h[MROWS * ENCC];
__device__ __align__(16) __nv_bfloat16 d_feat_l[MROWS * ENCC];
__device__ __align__(16) __nv_bfloat16 d_Wih_h[G4 * G4];
__device__ __align__(16) __nv_bfloat16 d_Wih_l[G4 * G4];
__device__ __align__(16) __nv_bfloat16 d_afW_h[ADIM * ENCC];
__device__ __align__(16) __nv_bfloat16 d_afW_l[ADIM * ENCC];
__device__ __align__(16) __nv_bfloat16 d_fcW_h[VPAD * HDIM];
__device__ __align__(16) __nv_bfloat16 d_fcW_l[VPAD * HDIM];
__device__ __align__(16) __nv_bfloat16 d_embbf_h[TSTEPS * NBATCH * EMBD];
__device__ __align__(16) __nv_bfloat16 d_embbf_l[TSTEPS * NBATCH * EMBD];
// t-major hidden outputs: [t*64+n][512]
__device__ __align__(16) __nv_bfloat16 d_houtbf_h[TSTEPS * NBATCH * HDIM];
__device__ __align__(16) __nv_bfloat16 d_houtbf_l[TSTEPS * NBATCH * HDIM];
// stacked small-GEMM weights: rows 0-511 attn_token_W, rows 512-2559 W_hh
__device__ __align__(16) __nv_bfloat16 d_sW_h[2560 * 512];
__device__ __align__(16) __nv_bfloat16 d_sW_l[2560 * 512];
// per-step h in bf16 hi/lo
__device__ __align__(16) __nv_bfloat16 d_hbf_h[NBATCH * HDIM];
__device__ __align__(16) __nv_bfloat16 d_hbf_l[NBATCH * HDIM];

__device__ __align__(16) __half d_attn_img[MROWS * ADIM];            // fp16, 4 MB
__device__ __align__(16) __half d_G[(size_t)NBATCH * G4 * NPIX];     // fp16, 16.7 MB
__device__ float d_pre[TSTEPS * NBATCH * G4];
__device__ float d_part[NSPLIT * 64 * 1024];       // init split-K partials (25MB)
__device__ float d_c[NBATCH * HDIM];
__device__ float d_P1[4 * NBATCH * ADIM];
__device__ float d_P3[4 * NBATCH * G4];
__device__ float d_logits[NBATCH * NPIX];

// =====================================================================
// warp-MMA + cp.async helpers (sm_80+ PTX, no arch-feature gating)
// =====================================================================
__device__ __forceinline__ uint32_t smem_u32(const void* p) {
    uint32_t a;
    asm("{ .reg .u64 t; cvta.to.shared.u64 t, %1; cvt.u32.u64 %0, t; }" : "=r"(a) : "l"(p));
    return a;
}
__device__ __forceinline__ void ldsm_x4(uint32_t* r, uint32_t addr) {
    asm volatile("ldmatrix.sync.aligned.m8n8.x4.shared.b16 {%0,%1,%2,%3}, [%4];"
                 : "=r"(r[0]), "=r"(r[1]), "=r"(r[2]), "=r"(r[3]) : "r"(addr));
}
__device__ __forceinline__ void ldsm_x4_t(uint32_t* r, uint32_t addr) {
    asm volatile("ldmatrix.sync.aligned.m8n8.x4.trans.shared.b16 {%0,%1,%2,%3}, [%4];"
                 : "=r"(r[0]), "=r"(r[1]), "=r"(r[2]), "=r"(r[3]) : "r"(addr));
}
__device__ __forceinline__ void mma_bf16(float* c, const uint32_t* a, const uint32_t* b) {
    asm volatile(
        "mma.sync.aligned.m16n8k16.row.col.f32.bf16.bf16.f32 "
        "{%0,%1,%2,%3}, {%4,%5,%6,%7}, {%8,%9}, {%0,%1,%2,%3};"
        : "+f"(c[0]), "+f"(c[1]), "+f"(c[2]), "+f"(c[3])
        : "r"(a[0]), "r"(a[1]), "r"(a[2]), "r"(a[3]), "r"(b[0]), "r"(b[1]));
}
__device__ __forceinline__ void cp16(uint32_t dst, const void* src, bool pred) {
    int sz = pred ? 16 : 0;
    asm volatile("cp.async.cg.shared.global [%0], [%1], 16, %2;"
                 :: "r"(dst), "l"(src), "r"(sz) : "memory");
}
#define CP_COMMIT() asm volatile("cp.async.commit_group;" ::: "memory")
#define CP_WAIT1()  asm volatile("cp.async.wait_group 1;" ::: "memory")

// =====================================================================
// Fused fp32 -> bf16 hi/lo conversion (6 segments).
// =====================================================================
__global__ void cvt_all(const float* __restrict__ feat,
                        const float* __restrict__ Wih,
                        const float* __restrict__ afW,
                        const float* __restrict__ fcW,
                        const float* __restrict__ tokW,
                        const float* __restrict__ Whh)
{
    int b = blockIdx.x;
    const float* src;
    __nv_bfloat16 *dh, *dl;
    int n_src, lb;
    if (b < 6144)       { src = feat; dh = d_feat_h; dl = d_feat_l; n_src = MROWS * ENCC; lb = b; }
    else if (b < 10240) { src = Wih;  dh = d_Wih_h;  dl = d_Wih_l;  n_src = G4 * G4;      lb = b - 6144; }
    else if (b < 11008) { src = afW;  dh = d_afW_h;  dl = d_afW_l;  n_src = ADIM * ENCC;  lb = b - 10240; }
    else if (b < 16032) { src = fcW;  dh = d_fcW_h;  dl = d_fcW_l;  n_src = VOCAB * HDIM; lb = b - 11008; }
    else if (b < 16288) { src = tokW; dh = d_sW_h;   dl = d_sW_l;   n_src = 512 * 512;    lb = b - 16032; }
    else                { src = Whh;  dh = d_sW_h + 262144; dl = d_sW_l + 262144;
                          n_src = 2048 * 512; lb = b - 16288; }
    int i = (lb * 256 + threadIdx.x) * 4;
    float4 v = make_float4(0.f, 0.f, 0.f, 0.f);
    if (i < n_src) v = *(const float4*)&src[i];
    float a[4] = {v.x, v.y, v.z, v.w};
    __nv_bfloat16 h[4], l[4];
#pragma unroll
    for (int j = 0; j < 4; j++) {
        h[j] = __float2bfloat16(a[j]);
        l[j] = __float2bfloat16(a[j] - __bfloat162float(h[j]));
    }
    *(__nv_bfloat162*)&dh[i]     = __halves2bfloat162(h[0], h[1]);
    *(__nv_bfloat162*)&dh[i + 2] = __halves2bfloat162(h[2], h[3]);
    *(__nv_bfloat162*)&dl[i]     = __halves2bfloat162(l[0], l[1]);
    *(__nv_bfloat162*)&dl[i + 2] = __halves2bfloat162(l[2], l[3]);
}

// embedding gather straight into bf16 hi/lo [t*64+n][e]
__global__ void emb_gather_bf(const int* __restrict__ cap,
                              const float* __restrict__ EW,
                              __nv_bfloat16* __restrict__ dh,
                              __nv_bfloat16* __restrict__ dl)
{
    int m = blockIdx.x;                 // t*64+n
    int n = m & 63, t = m >> 6;
    int tok = cap[n * TSTEPS + t];
    int i = threadIdx.x * 4;            // 128 thr * 4 = 512
    float4 v = *(const float4*)&EW[(size_t)tok * EMBD + i];
    float a[4] = {v.x, v.y, v.z, v.w};
    __nv_bfloat16 h[4], l[4];
#pragma unroll
    for (int j = 0; j < 4; j++) {
        h[j] = __float2bfloat16(a[j]);
        l[j] = __float2bfloat16(a[j] - __bfloat162float(h[j]));
    }
    size_t o = (size_t)m * EMBD + i;
    *(__nv_bfloat162*)&dh[o]     = __halves2bfloat162(h[0], h[1]);
    *(__nv_bfloat162*)&dh[o + 2] = __halves2bfloat162(h[2], h[3]);
    *(__nv_bfloat162*)&dl[o]     = __halves2bfloat162(l[0], l[1]);
    *(__nv_bfloat162*)&dl[o + 2] = __halves2bfloat162(l[2], l[3]);
}

// =====================================================================
// Warp-MMA NT GEMM, bf16 hi/lo split, fp32 accumulate, cp.async 2-stage.
// mode 0: fp32 C[m*ldc+n] (+bias)
// mode 3: merged — blockIdx.x<8: attn_img fp16 (+bias); else G fp16 layout
// mode 5: FC chunk — A rows are t-major (m = t*64+n within chunk, global
//         row = moff+m); store to C[((m&63... ) see below] with bias.
// =====================================================================
#define ASTR 72
#define AH_OFF 0
#define AL_OFF 18432
#define BH_OFF 36864
#define BL_OFF 46080
#define STAGE_BYTES 55296
#define MMA_SMEM_BYTES (2 * STAGE_BYTES)

__global__ void __launch_bounds__(256) mma_nt(
    const __nv_bfloat16* __restrict__ Ah, const __nv_bfloat16* __restrict__ Al,
    int lda, int Mvalid,
    const __nv_bfloat16* __restrict__ Bh, const __nv_bfloat16* __restrict__ Bl,
    int ldb,
    float* __restrict__ C, int Nvalid, int ldc,
    int chunks, const float* __restrict__ bias, int mode, int moff)
{
    extern __shared__ char smem[];
    const uint32_t sb = smem_u32(smem);
    const int tid = threadIdx.x, lane = tid & 31, wid = tid >> 5;
    const int wm = wid >> 1, wn = wid & 1;
    const int m0 = blockIdx.y * 128;

    const __nv_bfloat16* bH = Bh;
    const __nv_bfloat16* bL = Bl;
    const float* bptr = bias;
    int n0 = blockIdx.x * 64;
    int mode_eff = mode;
    if (mode == 3) {
        if (blockIdx.x < 8) {
            mode_eff = 4;
        } else {
            bH = d_Wih_h; bL = d_Wih_l; ldb = G4;
            bptr = nullptr;
            n0 = (blockIdx.x - 8) * 64;
            mode_eff = 1;
        }
    }

    float acc[2][4][4];
#pragma unroll
    for (int i = 0; i < 2; i++)
#pragma unroll
        for (int j = 0; j < 4; j++)
#pragma unroll
            for (int q = 0; q < 4; q++) acc[i][j][q] = 0.f;

    const uint32_t a_row = wm * 32 + (lane & 15);
    const uint32_t a_k   = ((lane >> 4) & 1) * 8;
    const uint32_t b_row = wn * 32 + (lane & 7) + ((lane >> 4) & 1) * 8;
    const uint32_t b_k   = ((lane >> 3) & 1) * 8;

    auto load_stage = [&](int ic, int st) {
        const uint32_t stb = sb + st * STAGE_BYTES;
        const long long kc = (long long)ic * 64;
#pragma unroll
        for (int it = 0; it < 4; it++) {
            int idx = it * 256 + tid;
            int row = idx >> 3, k8 = (idx & 7) * 8;
            int m = m0 + row;
            bool p = (m < Mvalid);
            int mc = p ? m : (Mvalid - 1);
            uint32_t off = (row * ASTR + k8) * 2;
            cp16(stb + AH_OFF + off, &Ah[(size_t)mc * lda + kc + k8], p);
            cp16(stb + AL_OFF + off, &Al[(size_t)mc * lda + kc + k8], p);
        }
#pragma unroll
        for (int it = 0; it < 2; it++) {
            int idx = it * 256 + tid;
            int row = idx >> 3, k8 = (idx & 7) * 8;
            uint32_t off = (row * ASTR + k8) * 2;
            cp16(stb + BH_OFF + off, &bH[(size_t)(n0 + row) * ldb + kc + k8], true);
            cp16(stb + BL_OFF + off, &bL[(size_t)(n0 + row) * ldb + kc + k8], true);
        }
    };

    load_stage(0, 0);
    CP_COMMIT();

    for (int ic = 0; ic < chunks; ic++) {
        const int s = ic & 1;
        if (ic + 1 < chunks) load_stage(ic + 1, s ^ 1);
        CP_COMMIT();
        CP_WAIT1();
        __syncthreads();

        const uint32_t stb = sb + s * STAGE_BYTES;
#pragma unroll
        for (int ks = 0; ks < 4; ks++) {
            const uint32_t k16 = ks * 16;
            uint32_t ahf[2][4], alf[2][4], bhf[2][4], blf[2][4];
#pragma unroll
            for (int mt = 0; mt < 2; mt++) {
                uint32_t off = ((a_row + mt * 16) * ASTR + k16 + a_k) * 2;
                ldsm_x4(ahf[mt], stb + AH_OFF + off);
                ldsm_x4(alf[mt], stb + AL_OFF + off);
            }
#pragma unroll
            for (int np = 0; np < 2; np++) {
                uint32_t off = ((b_row + np * 16) * ASTR + k16 + b_k) * 2;
                ldsm_x4(bhf[np], stb + BH_OFF + off);
                ldsm_x4(blf[np], stb + BL_OFF + off);
            }
#pragma unroll
            for (int mt = 0; mt < 2; mt++)
#pragma unroll
                for (int np = 0; np < 2; np++) {
                    mma_bf16(acc[mt][np * 2 + 0], ahf[mt], &bhf[np][0]);
                    mma_bf16(acc[mt][np * 2 + 1], ahf[mt], &bhf[np][2]);
                    mma_bf16(acc[mt][np * 2 + 0], ahf[mt], &blf[np][0]);
                    mma_bf16(acc[mt][np * 2 + 1], ahf[mt], &blf[np][2]);
                    mma_bf16(acc[mt][np * 2 + 0], alf[mt], &bhf[np][0]);
                    mma_bf16(acc[mt][np * 2 + 1], alf[mt], &bhf[np][2]);
                }
        }
        __syncthreads();
    }

    const int g = lane >> 2, tg = lane & 3;
#pragma unroll
    for (int mt = 0; mt < 2; mt++) {
#pragma unroll
        for (int nt = 0; nt < 4; nt++) {
            int r0 = m0 + wm * 32 + mt * 16 + g;
            int c0 = n0 + wn * 32 + nt * 8 + tg * 2;
#pragma unroll
            for (int q = 0; q < 4; q++) {
                int m = r0 + (q >> 1) * 8;
                int n = c0 + (q & 1);
                if (m >= Mvalid) continue;
                float v = acc[mt][nt][q];
                if (mode_eff == 1) {
                    int nb = m >> 6, p = m & 63;
                    d_G[((size_t)nb * 2048 + n) * 64 + p] = __float2half(v);
                } else if (mode_eff == 4) {
                    d_attn_img[(size_t)m * ADIM + n] = __float2half(v + bptr[n]);
                } else if (mode_eff == 5) {
                    if (n < Nvalid) {
                        int gm = moff + m;          // global row, t-major
                        int tt = gm >> 6, nb = gm & 63;
                        C[(size_t)(nb * TSTEPS + tt) * ldc + n] = v + bptr[n];
                    }
                } else {
                    if (n < Nvalid) {
                        if (bptr) v += bptr[n];
                        C[(size_t)m * ldc + n] = v;
                    }
                }
            }
        }
    }
}

// =====================================================================
// Fused init GEMM: h0|c0 = F(64x98304) @ [Wh|Wc]; split-K 96.
// =====================================================================
#define IBSTR 136
#define IA_H 0
#define IA_L 9216
#define IB_H 18432
#define IB_L 35840
#define INIT_SMEM_BYTES 53248

__global__ void __launch_bounds__(256) init_mma(
    const float* __restrict__ Wh, const float* __restrict__ Wc,
    float* __restrict__ P)
{
    extern __shared__ char smem[];
    const uint32_t sb = smem_u32(smem);
    __nv_bfloat16* Bsh = (__nv_bfloat16*)(smem + IB_H);
    __nv_bfloat16* Bsl = (__nv_bfloat16*)(smem + IB_L);
    const int tid = threadIdx.x, lane = tid & 31, wid = tid >> 5;
    const int wm = wid >> 2, wn = wid & 3;
    const int bx = blockIdx.x;
    const float* __restrict__ W = (bx < 4) ? Wh : Wc;
    const int n0g = (bx & 3) * 128;
    const int outc0 = bx * 128;
    const size_t k0 = (size_t)blockIdx.y * 1024;

    float acc[2][4][4];
#pragma unroll
    for (int i = 0; i < 2; i++)
#pragma unroll
        for (int j = 0; j < 4; j++)
#pragma unroll
            for (int q = 0; q < 4; q++) acc[i][j][q] = 0.f;

    const uint32_t a_row = wm * 32 + (lane & 15);
    const uint32_t a_k   = ((lane >> 4) & 1) * 8;
    const uint32_t bt_k = ((lane >> 3) & 1) * 8 + (lane & 7);
    const uint32_t bt_n = ((lane >> 4) & 1) * 8;

    for (int ic = 0; ic < 16; ic++) {
        const size_t kg = k0 + ic * 64;
#pragma unroll
        for (int it = 0; it < 2; it++) {
            int idx = it * 256 + tid;
            int row = idx >> 3, k8 = (idx & 7) * 8;
            uint32_t off = (row * ASTR + k8) * 2;
            *(uint4*)(smem + IA_H + off) = *(const uint4*)&d_feat_h[(size_t)row * KINIT + kg + k8];
            *(uint4*)(smem + IA_L + off) = *(const uint4*)&d_feat_l[(size_t)row * KINIT + kg + k8];
        }
#pragma unroll
        for (int it = 0; it < 8; it++) {
            int idx = it * 256 + tid;
            int kk = idx >> 5, nn = (idx & 31) * 4;
            float4 v = *(const float4*)&W[(kg + kk) * 512 + n0g + nn];
            float a[4] = {v.x, v.y, v.z, v.w};
            __nv_bfloat16 h[4], l[4];
#pragma unroll
            for (int j = 0; j < 4; j++) {
                h[j] = __float2bfloat16(a[j]);
                l[j] = __float2bfloat16(a[j] - __bfloat162float(h[j]));
            }
            int o = kk * IBSTR + nn;
            *(__nv_bfloat162*)&Bsh[o]     = __halves2bfloat162(h[0], h[1]);
            *(__nv_bfloat162*)&Bsh[o + 2] = __halves2bfloat162(h[2], h[3]);
            *(__nv_bfloat162*)&Bsl[o]     = __halves2bfloat162(l[0], l[1]);
            *(__nv_bfloat162*)&Bsl[o + 2] = __halves2bfloat162(l[2], l[3]);
        }
        __syncthreads();

#pragma unroll
        for (int ks = 0; ks < 4; ks++) {
            const uint32_t k16 = ks * 16;
            uint32_t ahf[2][4], alf[2][4];
#pragma unroll
            for (int mt = 0; mt < 2; mt++) {
                uint32_t off = ((a_row + mt * 16) * ASTR + k16 + a_k) * 2;
                ldsm_x4(ahf[mt], sb + IA_H + off);
                ldsm_x4(alf[mt], sb + IA_L + off);
            }
#pragma unroll
            for (int ng = 0; ng < 2; ng++) {
                uint32_t bhf[4], blf[4];
                uint32_t off = ((k16 + bt_k) * IBSTR + wn * 32 + ng * 16 + bt_n) * 2;
                ldsm_x4_t(bhf, sb + IB_H + off);
                ldsm_x4_t(blf, sb + IB_L + off);
#pragma unroll
                for (int mt = 0; mt < 2; mt++) {
                    mma_bf16(acc[mt][ng * 2 + 0], ahf[mt], &bhf[0]);
                    mma_bf16(acc[mt][ng * 2 + 1], ahf[mt], &bhf[2]);
                    mma_bf16(acc[mt][ng * 2 + 0], ahf[mt], &blf[0]);
                    mma_bf16(acc[mt][ng * 2 + 1], ahf[mt], &blf[2]);
                    mma_bf16(acc[mt][ng * 2 + 0], alf[mt], &bhf[0]);
                    mma_bf16(acc[mt][ng * 2 + 1], alf[mt], &bhf[2]);
                }
            }
        }
        __syncthreads();
    }

    const int g = lane >> 2, tg = lane & 3;
    const int zb = blockIdx.y * 64;
#pragma unroll
    for (int mt = 0; mt < 2; mt++)
#pragma unroll
        for (int nt = 0; nt < 4; nt++) {
            int r0 = wm * 32 + mt * 16 + g;
            int c0 = outc0 + wn * 32 + nt * 8 + tg * 2;
#pragma unroll
            for (int q = 0; q < 4; q++) {
                int m = r0 + (q >> 1) * 8;
                int n = c0 + (q & 1);
                P[(size_t)(zb + m) * 1024 + n] = acc[mt][nt][q];
            }
        }
}

// deterministic reduce of NSPLIT split-K partials -> h0 (bf16 hi/lo), c0
__global__ void reduce_init(const float* __restrict__ P,
                            float* __restrict__ c)
{
    int r = blockIdx.x * 256 + threadIdx.x;   // 65536
    float s = 0.f;
#pragma unroll
    for (int j = 0; j < NSPLIT; j++) s += P[(size_t)j * 65536 + r];
    int m = r >> 10, col = r & 1023;
    if (col < 512) {
        __nv_bfloat16 hi = __float2bfloat16(s);
        d_hbf_h[m * 512 + col] = hi;
        d_hbf_l[m * 512 + col] = __float2bfloat16(s - __bfloat162float(hi));
    } else {
        c[m * 512 + col - 512] = s;
    }
}

// =====================================================================
// Per-step small GEMM on TENSOR CORES (R11): [P1|P3] partials.
// grid (40 cb, 4 ks), 128 threads.
// =====================================================================
#define SSTR 136
#define S_AH 0
#define S_AL 17408
#define S_BH 34816
#define S_BL 52224
#define SMALL_SMEM 69632

__global__ void __launch_bounds__(128) small_mma(
    float* __restrict__ P1o, float* __restrict__ P3o)
{
    extern __shared__ char smem[];
    const uint32_t sb = smem_u32(smem);
    const int tid = threadIdx.x, lane = tid & 31, wid = tid >> 5;
    const int wm = wid >> 1, wn = wid & 1;
    const int cb = blockIdx.x, ks = blockIdx.y;
    const int k0 = ks * 128;

    float* __restrict__ P;
    int Ncols, cbl;
    if (cb < 8) { P = P1o; Ncols = 512;  cbl = cb; }
    else        { P = P3o; Ncols = 2048; cbl = cb - 8; }

#pragma unroll
    for (int it = 0; it < 8; it++) {
        int idx = it * 128 + tid;
        int row = idx >> 4, c8 = (idx & 15) * 8;
        uint32_t off = (row * SSTR + c8) * 2;
        *(uint4*)(smem + S_AH + off) = *(const uint4*)&d_hbf_h[row * 512 + k0 + c8];
        *(uint4*)(smem + S_AL + off) = *(const uint4*)&d_hbf_l[row * 512 + k0 + c8];
        *(uint4*)(smem + S_BH + off) = *(const uint4*)&d_sW_h[(size_t)(cb * 64 + row) * 512 + k0 + c8];
        *(uint4*)(smem + S_BL + off) = *(const uint4*)&d_sW_l[(size_t)(cb * 64 + row) * 512 + k0 + c8];
    }
    __syncthreads();

    float acc[2][4][4];
#pragma unroll
    for (int i = 0; i < 2; i++)
#pragma unroll
        for (int j = 0; j < 4; j++)
#pragma unroll
            for (int q = 0; q < 4; q++) acc[i][j][q] = 0.f;

    const uint32_t a_row = wm * 32 + (lane & 15);
    const uint32_t a_k   = ((lane >> 4) & 1) * 8;
    const uint32_t b_row = wn * 32 + (lane & 7) + ((lane >> 4) & 1) * 8;
    const uint32_t b_k   = ((lane >> 3) & 1) * 8;

#pragma unroll
    for (int k16i = 0; k16i < 8; k16i++) {
        const uint32_t k16 = k16i * 16;
        uint32_t ahf[2][4], alf[2][4], bhf[2][4], blf[2][4];
#pragma unroll
        for (int mt = 0; mt < 2; mt++) {
            uint32_t off = ((a_row + mt * 16) * SSTR + k16 + a_k) * 2;
            ldsm_x4(ahf[mt], sb + S_AH + off);
            ldsm_x4(alf[mt], sb + S_AL + off);
        }
#pragma unroll
        for (int np = 0; np < 2; np++) {
            uint32_t off = ((b_row + np * 16) * SSTR + k16 + b_k) * 2;
            ldsm_x4(bhf[np], sb + S_BH + off);
            ldsm_x4(blf[np], sb + S_BL + off);
        }
#pragma unroll
        for (int mt = 0; mt < 2; mt++)
#pragma unroll
            for (int np = 0; np < 2; np++) {
                mma_bf16(acc[mt][np * 2 + 0], ahf[mt], &bhf[np][0]);
                mma_bf16(acc[mt][np * 2 + 1], ahf[mt], &bhf[np][2]);
                mma_bf16(acc[mt][np * 2 + 0], ahf[mt], &blf[np][0]);
                mma_bf16(acc[mt][np * 2 + 1], ahf[mt], &blf[np][2]);
                mma_bf16(acc[mt][np * 2 + 0], alf[mt], &bhf[np][0]);
                mma_bf16(acc[mt][np * 2 + 1], alf[mt], &bhf[np][2]);
            }
    }

    const int g = lane >> 2, tg = lane & 3;
#pragma unroll
    for (int mt = 0; mt < 2; mt++)
#pragma unroll
        for (int nt = 0; nt < 4; nt++) {
            int r0 = wm * 32 + mt * 16 + g;
            int c0 = cbl * 64 + wn * 32 + nt * 8 + tg * 2;
#pragma unroll
            for (int q = 0; q < 4; q++) {
                int m = r0 + (q >> 1) * 8;
                int n = c0 + (q & 1);
                P[(size_t)(ks * 64 + m) * Ncols + n] = acc[mt][nt][q];
            }
        }
}

// =====================================================================
// Attention scores + softmax (attn_img fp16)
// =====================================================================
__global__ void attn_softmax(const float* __restrict__ P1,
                             const float* __restrict__ tb,
                             const float* __restrict__ wfull)
{
    const int n = blockIdx.x, tid = threadIdx.x;
    __shared__ float ah[512], wf[512], sc[64];
    float v = tb[tid];
#pragma unroll
    for (int s = 0; s < 4; s++) v += P1[(size_t)(s * 64 + n) * 512 + tid];
    ah[tid] = v;
    wf[tid] = wfull[tid];
    __syncthreads();

    const int warp = tid >> 5, lane = tid & 31;
    for (int p = warp; p < 64; p += 16) {
        const __half* img = &d_attn_img[(size_t)(n * 64 + p) * 512];
        float s = 0.f;
#pragma unroll
        for (int a = lane; a < 512; a += 32) {
            float e = ah[a] + __half2float(img[a]);
            if (e > 0.f) s += e * wf[a];
        }
#pragma unroll
        for (int o = 16; o > 0; o >>= 1) s += __shfl_xor_sync(0xFFFFFFFFu, s, o);
        if (lane == 0) sc[p] = s;
    }
    __syncthreads();
    if (tid < 32) {
        float s0 = sc[tid], s1 = sc[tid + 32];
        float mx = fmaxf(s0, s1);
#pragma unroll
        for (int o = 16; o > 0; o >>= 1) mx = fmaxf(mx, __shfl_xor_sync(0xFFFFFFFFu, mx, o));
        float e0 = expf(s0 - mx), e1 = expf(s1 - mx);
        float sum = e0 + e1;
#pragma unroll
        for (int o = 16; o > 0; o >>= 1) sum += __shfl_xor_sync(0xFFFFFFFFu, sum, o);
        float inv = 1.f / sum;
        d_logits[n * 64 + tid]      = e0 * inv;
        d_logits[n * 64 + tid + 32] = e1 * inv;
    }
}

// =====================================================================
// Gates assembly + LSTM pointwise (G fp16); h out t-major for FC chunks.
// grid (64 n, 8 hchunk), 256 threads.
// =====================================================================
__global__ void gates_lstm(const float* __restrict__ P3,
                           const float* __restrict__ pre_t,
                           const float* __restrict__ b_ih,
                           const float* __restrict__ b_hh,
                           int t)
{
    const int n = blockIdx.x, hc = blockIdx.y, tid = threadIdx.x;
    __shared__ float lg[64];
    __shared__ float sg[4][64];
    if (tid < 64) lg[tid] = d_logits[n * 64 + tid];
    __syncthreads();

    const int q = tid >> 6, hl = tid & 63;
    const int j = q * 512 + hc * 64 + hl;
    float acc = b_ih[j] + b_hh[j] + pre_t[n * 2048 + j];
#pragma unroll
    for (int s = 0; s < 4; s++) acc += P3[(size_t)(s * 64 + n) * 2048 + j];
    const uint4* g4 = (const uint4*)&d_G[((size_t)n * 2048 + j) * 64];
#pragma unroll
    for (int pi = 0; pi < 8; pi++) {
        uint4 u = g4[pi];
        __half2 h0 = *(__half2*)&u.x, h1 = *(__half2*)&u.y;
        __half2 h2 = *(__half2*)&u.z, h3 = *(__half2*)&u.w;
        float2 f0 = __half22float2(h0), f1 = __half22float2(h1);
        float2 f2 = __half22float2(h2), f3 = __half22float2(h3);
        const float* w = &lg[pi * 8];
        acc += w[0] * f0.x + w[1] * f0.y + w[2] * f1.x + w[3] * f1.y
             + w[4] * f2.x + w[5] * f2.y + w[6] * f3.x + w[7] * f3.y;
    }
    sg[q][hl] = acc;
    __syncthreads();

    if (tid < 64) {
        int hidx = hc * 64 + tid;
        float ig = sg[0][tid], fg = sg[1][tid], gg = sg[2][tid], og = sg[3][tid];
        float si = 1.f / (1.f + expf(-ig));
        float sf = 1.f / (1.f + expf(-fg));
        float so = 1.f / (1.f + expf(-og));
        float cn = sf * d_c[n * 512 + hidx] + si * tanhf(gg);
        float hn = so * tanhf(cn);
        d_c[n * 512 + hidx] = cn;
        __nv_bfloat16 hi = __float2bfloat16(hn);
        __nv_bfloat16 lo = __float2bfloat16(hn - __bfloat162float(hi));
        d_hbf_h[n * 512 + hidx] = hi;
        d_hbf_l[n * 512 + hidx] = lo;
        size_t o = ((size_t)t * NBATCH + n) * 512 + hidx;   // t-major
        d_houtbf_h[o] = hi;
        d_houtbf_l[o] = lo;
    }
}

// =====================================================================
// Host side
// =====================================================================
template <typename Tp>
static void* symaddr(Tp& ref)
{
    void* p = nullptr;
    cudaGetSymbolAddress(&p, ref);
    return p;
}

extern "C" void kernel_launch(void* const* d_in, const int* in_sizes, int n_in,
                              void* d_out, int out_size)
{
    const float* features     = (const float*)d_in[0];
    const int*   captions     = (const int*)  d_in[1];
    const float* embd_W       = (const float*)d_in[2];
    const float* attn_token_W = (const float*)d_in[3];
    const float* attn_token_b = (const float*)d_in[4];
    const float* attn_feat_W  = (const float*)d_in[5];
    const float* attn_feat_b  = (const float*)d_in[6];
    const float* attn_full_W  = (const float*)d_in[7];
    // d_in[8] attn_full_b: softmax-invariant constant -> skipped
    const float* W_ih         = (const float*)d_in[9];
    const float* b_ih         = (const float*)d_in[10];
    const float* W_hh         = (const float*)d_in[11];
    const float* b_hh         = (const float*)d_in[12];
    const float* fc_W         = (const float*)d_in[13];
    const float* fc_b         = (const float*)d_in[14];
    const float* init_Wh      = (const float*)d_in[15];
    const float* init_Wc      = (const float*)d_in[16];
    float* out = (float*)d_out;

    __nv_bfloat16* p_feat_h = (__nv_bfloat16*)symaddr(d_feat_h);
    __nv_bfloat16* p_feat_l = (__nv_bfloat16*)symaddr(d_feat_l);
    __nv_bfloat16* p_Wih_h  = (__nv_bfloat16*)symaddr(d_Wih_h);
    __nv_bfloat16* p_Wih_l  = (__nv_bfloat16*)symaddr(d_Wih_l);
    __nv_bfloat16* p_afW_h  = (__nv_bfloat16*)symaddr(d_afW_h);
    __nv_bfloat16* p_afW_l  = (__nv_bfloat16*)symaddr(d_afW_l);
    __nv_bfloat16* p_fcW_h  = (__nv_bfloat16*)symaddr(d_fcW_h);
    __nv_bfloat16* p_fcW_l  = (__nv_bfloat16*)symaddr(d_fcW_l);
    __nv_bfloat16* p_emb_h  = (__nv_bfloat16*)symaddr(d_embbf_h);
    __nv_bfloat16* p_emb_l  = (__nv_bfloat16*)symaddr(d_embbf_l);
    __nv_bfloat16* p_hbf_h  = (__nv_bfloat16*)symaddr(d_houtbf_h);
    __nv_bfloat16* p_hbf_l  = (__nv_bfloat16*)symaddr(d_houtbf_l);

    float* p_pre  = (float*)symaddr(d_pre);
    float* p_part = (float*)symaddr(d_part);
    float* p_c    = (float*)symaddr(d_c);
    float* p_P1   = (float*)symaddr(d_P1);
    float* p_P3   = (float*)symaddr(d_P3);

    // opt-in to >48KB dynamic smem (idempotent)
    cudaFuncAttributes fa;
    cudaFuncGetAttributes(&fa, mma_nt);
    if (fa.maxDynamicSharedSizeBytes < MMA_SMEM_BYTES)
        cudaFuncSetAttribute(mma_nt, cudaFuncAttributeMaxDynamicSharedMemorySize,
                             MMA_SMEM_BYTES);
    cudaFuncGetAttributes(&fa, init_mma);
    if (fa.maxDynamicSharedSizeBytes < INIT_SMEM_BYTES)
        cudaFuncSetAttribute(init_mma, cudaFuncAttributeMaxDynamicSharedMemorySize,
                             INIT_SMEM_BYTES);
    cudaFuncGetAttributes(&fa, small_mma);
    if (fa.maxDynamicSharedSizeBytes < SMALL_SMEM)
        cudaFuncSetAttribute(small_mma, cudaFuncAttributeMaxDynamicSharedMemorySize,
                             SMALL_SMEM);

    // side stream + events (host-side objects only)
    static cudaStream_t s2 = nullptr;
    static cudaEvent_t evA = nullptr, evB = nullptr, evF = nullptr;
    static cudaEvent_t evS[8] = {};
    if (!s2) {
        cudaStreamCreateWithFlags(&s2, cudaStreamNonBlocking);
        cudaEventCreateWithFlags(&evA, cudaEventDisableTiming);
        cudaEventCreateWithFlags(&evB, cudaEventDisableTiming);
        cudaEventCreateWithFlags(&evF, cudaEventDisableTiming);
        for (int k = 0; k < 8; k++)
            cudaEventCreateWithFlags(&evS[k], cudaEventDisableTiming);
    }

    // ---- conversions (stream 0) ----
    cvt_all<<<17312, 256>>>(features, W_ih, attn_feat_W, fc_W,
                            attn_token_W, W_hh);
    cudaEventRecord(evA, 0);

    // ---- fork: init GEMM chain on s2 ----
    cudaStreamWaitEvent(s2, evA, 0);
    init_mma<<<dim3(8, NSPLIT), 256, INIT_SMEM_BYTES, s2>>>(init_Wh, init_Wc, p_part);
    reduce_init<<<256, 256, 0, s2>>>(p_part, p_c);
    cudaEventRecord(evB, s2);

    // ---- stream 0: remaining prologue ----
    emb_gather_bf<<<TSTEPS * NBATCH, 128>>>(captions, embd_W, p_emb_h, p_emb_l);
    // pre_emb = emb @ W_ih[:,1536:]^T  (2048 x 2048, K=512)
    mma_nt<<<dim3(32, 16, 1), 256, MMA_SMEM_BYTES>>>(
        p_emb_h, p_emb_l, EMBD, TSTEPS * NBATCH, p_Wih_h + 1536, p_Wih_l + 1536, G4,
        p_pre, G4, G4, 8, nullptr, 0, 0);
    // merged: attn_img (fp16) + G (fp16)
    mma_nt<<<dim3(40, 32, 1), 256, MMA_SMEM_BYTES>>>(
        p_feat_h, p_feat_l, ENCC, MROWS, p_afW_h, p_afW_l, ENCC,
        nullptr, ADIM, ADIM, 24, attn_feat_b, 3, 0);

    // ---- join: h0/c0 ready before the recurrence ----
    cudaStreamWaitEvent((cudaStream_t)0, evB, 0);

    // ---- sequential recurrence with FC chunks overlapped on s2 ----
    for (int t = 0; t < TSTEPS; ++t) {
        small_mma<<<dim3(40, 4), 128, SMALL_SMEM>>>(p_P1, p_P3);
        attn_softmax<<<64, 512>>>(p_P1, attn_token_b, attn_full_W);
        gates_lstm<<<dim3(64, 8), 256>>>(p_P3, p_pre + (size_t)t * NBATCH * G4,
                                         b_ih, b_hh, t);
        if ((t & 3) == 3) {
            int k = t >> 2;
            cudaEventRecord(evS[k], 0);
            cudaStreamWaitEvent(s2, evS[k], 0);
            // FC chunk: rows [k*256, k*256+256) of t-major hout
            mma_nt<<<dim3(157, 2, 1), 256, MMA_SMEM_BYTES, s2>>>(
                p_hbf_h + (size_t)k * 256 * HDIM,
                p_hbf_l + (size_t)k * 256 * HDIM, HDIM, 256,
                p_fcW_h, p_fcW_l, HDIM,
                out, VOCAB, VOCAB, 8, fc_b, 5, k * 256);
        }
    }

    // ---- join: all FC chunks done ----
    cudaEventRecord(evF, s2);
    cudaStreamWaitEvent((cudaStream_t)0, evF, 0);
}

// round 15
// speedup vs baseline: 1.1267x; 1.0100x over previous
#include <cuda_runtime.h>
#include <cuda_bf16.h>
#include <cuda_fp16.h>
#include <cstdint>
#include <math.h>

// ---------------- problem constants ----------------
#define TSTEPS 32
#define NBATCH 64
#define NPIX   64
#define ENCC   1536
#define EMBD   512
#define ADIM   512
#define HDIM   512
#define G4     2048     // 4*H
#define VOCAB  10000
#define VPAD   10048    // 157*64
#define MROWS  4096     // N*P
#define KINIT  98304    // P*ENC
#define NSPLIT 96       // init split-K

// ---------------- scratch (__device__ globals; no allocation) ----------------
__device__ __align__(16) __nv_bfloat16 d_feat_h[MROWS * ENCC];
__device__ __align__(16) __nv_bfloat16 d_feat_l[MROWS * ENCC];
__device__ __align__(16) __nv_bfloat16 d_Wih_h[G4 * G4];
__device__ __align__(16) __nv_bfloat16 d_Wih_l[G4 * G4];
__device__ __align__(16) __nv_bfloat16 d_afW_h[ADIM * ENCC];
__device__ __align__(16) __nv_bfloat16 d_afW_l[ADIM * ENCC];
__device__ __align__(16) __nv_bfloat16 d_fcW_h[VPAD * HDIM];
__device__ __align__(16) __nv_bfloat16 d_fcW_l[VPAD * HDIM];
__device__ __align__(16) __nv_bfloat16 d_embbf_h[TSTEPS * NBATCH * EMBD];
__device__ __align__(16) __nv_bfloat16 d_embbf_l[TSTEPS * NBATCH * EMBD];
// t-major hidden outputs: [t*64+n][512]
__device__ __align__(16) __nv_bfloat16 d_houtbf_h[TSTEPS * NBATCH * HDIM];
__device__ __align__(16) __nv_bfloat16 d_houtbf_l[TSTEPS * NBATCH * HDIM];
// stacked small-GEMM weights: rows 0-511 attn_token_W, rows 512-2559 W_hh
__device__ __align__(16) __nv_bfloat16 d_sW_h[2560 * 512];
__device__ __align__(16) __nv_bfloat16 d_sW_l[2560 * 512];
// per-step h in bf16 hi/lo
__device__ __align__(16) __nv_bfloat16 d_hbf_h[NBATCH * HDIM];
__device__ __align__(16) __nv_bfloat16 d_hbf_l[NBATCH * HDIM];

__device__ __align__(16) __half d_attn_img[MROWS * ADIM];            // fp16, 4 MB
__device__ __align__(16) __half d_G[(size_t)NBATCH * G4 * NPIX];     // fp16, 16.7 MB
__device__ float d_pre[TSTEPS * NBATCH * G4];
__device__ float d_part[NSPLIT * 64 * 1024];       // init split-K partials (25MB)
__device__ float d_c[NBATCH * HDIM];
__device__ float d_P1[4 * NBATCH * ADIM];
__device__ float d_P3[4 * NBATCH * G4];
__device__ float d_logits[NBATCH * NPIX];

// intra-launch ordering counter (monotonic across the 32 step launches)
__device__ unsigned g_cP1;

// =====================================================================
// warp-MMA + cp.async helpers (sm_80+ PTX, no arch-feature gating)
// =====================================================================
__device__ __forceinline__ uint32_t smem_u32(const void* p) {
    uint32_t a;
    asm("{ .reg .u64 t; cvta.to.shared.u64 t, %1; cvt.u32.u64 %0, t; }" : "=r"(a) : "l"(p));
    return a;
}
__device__ __forceinline__ void ldsm_x4(uint32_t* r, uint32_t addr) {
    asm volatile("ldmatrix.sync.aligned.m8n8.x4.shared.b16 {%0,%1,%2,%3}, [%4];"
                 : "=r"(r[0]), "=r"(r[1]), "=r"(r[2]), "=r"(r[3]) : "r"(addr));
}
__device__ __forceinline__ void ldsm_x4_t(uint32_t* r, uint32_t addr) {
    asm volatile("ldmatrix.sync.aligned.m8n8.x4.trans.shared.b16 {%0,%1,%2,%3}, [%4];"
                 : "=r"(r[0]), "=r"(r[1]), "=r"(r[2]), "=r"(r[3]) : "r"(addr));
}
__device__ __forceinline__ void mma_bf16(float* c, const uint32_t* a, const uint32_t* b) {
    asm volatile(
        "mma.sync.aligned.m16n8k16.row.col.f32.bf16.bf16.f32 "
        "{%0,%1,%2,%3}, {%4,%5,%6,%7}, {%8,%9}, {%0,%1,%2,%3};"
        : "+f"(c[0]), "+f"(c[1]), "+f"(c[2]), "+f"(c[3])
        : "r"(a[0]), "r"(a[1]), "r"(a[2]), "r"(a[3]), "r"(b[0]), "r"(b[1]));
}
__device__ __forceinline__ void cp16(uint32_t dst, const void* src, bool pred) {
    int sz = pred ? 16 : 0;
    asm volatile("cp.async.cg.shared.global [%0], [%1], 16, %2;"
                 :: "r"(dst), "l"(src), "r"(sz) : "memory");
}
#define CP_COMMIT() asm volatile("cp.async.commit_group;" ::: "memory")
#define CP_WAIT1()  asm volatile("cp.async.wait_group 1;" ::: "memory")

// =====================================================================
// Fused fp32 -> bf16 hi/lo conversion (6 segments).
// =====================================================================
__global__ void cvt_all(const float* __restrict__ feat,
                        const float* __restrict__ Wih,
                        const float* __restrict__ afW,
                        const float* __restrict__ fcW,
                        const float* __restrict__ tokW,
                        const float* __restrict__ Whh)
{
    int b = blockIdx.x;
    const float* src;
    __nv_bfloat16 *dh, *dl;
    int n_src, lb;
    if (b < 6144)       { src = feat; dh = d_feat_h; dl = d_feat_l; n_src = MROWS * ENCC; lb = b; }
    else if (b < 10240) { src = Wih;  dh = d_Wih_h;  dl = d_Wih_l;  n_src = G4 * G4;      lb = b - 6144; }
    else if (b < 11008) { src = afW;  dh = d_afW_h;  dl = d_afW_l;  n_src = ADIM * ENCC;  lb = b - 10240; }
    else if (b < 16032) { src = fcW;  dh = d_fcW_h;  dl = d_fcW_l;  n_src = VOCAB * HDIM; lb = b - 11008; }
    else if (b < 16288) { src = tokW; dh = d_sW_h;   dl = d_sW_l;   n_src = 512 * 512;    lb = b - 16032; }
    else                { src = Whh;  dh = d_sW_h + 262144; dl = d_sW_l + 262144;
                          n_src = 2048 * 512; lb = b - 16288; }
    int i = (lb * 256 + threadIdx.x) * 4;
    float4 v = make_float4(0.f, 0.f, 0.f, 0.f);
    if (i < n_src) v = *(const float4*)&src[i];
    float a[4] = {v.x, v.y, v.z, v.w};
    __nv_bfloat16 h[4], l[4];
#pragma unroll
    for (int j = 0; j < 4; j++) {
        h[j] = __float2bfloat16(a[j]);
        l[j] = __float2bfloat16(a[j] - __bfloat162float(h[j]));
    }
    *(__nv_bfloat162*)&dh[i]     = __halves2bfloat162(h[0], h[1]);
    *(__nv_bfloat162*)&dh[i + 2] = __halves2bfloat162(h[2], h[3]);
    *(__nv_bfloat162*)&dl[i]     = __halves2bfloat162(l[0], l[1]);
    *(__nv_bfloat162*)&dl[i + 2] = __halves2bfloat162(l[2], l[3]);
}

// embedding gather straight into bf16 hi/lo [t*64+n][e]
__global__ void emb_gather_bf(const int* __restrict__ cap,
                              const float* __restrict__ EW,
                              __nv_bfloat16* __restrict__ dh,
                              __nv_bfloat16* __restrict__ dl)
{
    int m = blockIdx.x;                 // t*64+n
    int n = m & 63, t = m >> 6;
    int tok = cap[n * TSTEPS + t];
    int i = threadIdx.x * 4;            // 128 thr * 4 = 512
    float4 v = *(const float4*)&EW[(size_t)tok * EMBD + i];
    float a[4] = {v.x, v.y, v.z, v.w};
    __nv_bfloat16 h[4], l[4];
#pragma unroll
    for (int j = 0; j < 4; j++) {
        h[j] = __float2bfloat16(a[j]);
        l[j] = __float2bfloat16(a[j] - __bfloat162float(h[j]));
    }
    size_t o = (size_t)m * EMBD + i;
    *(__nv_bfloat162*)&dh[o]     = __halves2bfloat162(h[0], h[1]);
    *(__nv_bfloat162*)&dh[o + 2] = __halves2bfloat162(h[2], h[3]);
    *(__nv_bfloat162*)&dl[o]     = __halves2bfloat162(l[0], l[1]);
    *(__nv_bfloat162*)&dl[o + 2] = __halves2bfloat162(l[2], l[3]);
}

// =====================================================================
// Warp-MMA NT GEMM, bf16 hi/lo split, fp32 accumulate, cp.async 2-stage.
// mode 0: fp32 C[m*ldc+n] (+bias)
// mode 3: merged — blockIdx.x<8: attn_img fp16 (+bias); else G fp16 layout
// mode 5: FC — A rows t-major (global row = moff+m), store [n][t][v] +bias
// =====================================================================
#define ASTR 72
#define AH_OFF 0
#define AL_OFF 18432
#define BH_OFF 36864
#define BL_OFF 46080
#define STAGE_BYTES 55296
#define MMA_SMEM_BYTES (2 * STAGE_BYTES)

__global__ void __launch_bounds__(256) mma_nt(
    const __nv_bfloat16* __restrict__ Ah, const __nv_bfloat16* __restrict__ Al,
    int lda, int Mvalid,
    const __nv_bfloat16* __restrict__ Bh, const __nv_bfloat16* __restrict__ Bl,
    int ldb,
    float* __restrict__ C, int Nvalid, int ldc,
    int chunks, const float* __restrict__ bias, int mode, int moff)
{
    extern __shared__ char smem[];
    const uint32_t sb = smem_u32(smem);
    const int tid = threadIdx.x, lane = tid & 31, wid = tid >> 5;
    const int wm = wid >> 1, wn = wid & 1;
    const int m0 = blockIdx.y * 128;

    const __nv_bfloat16* bH = Bh;
    const __nv_bfloat16* bL = Bl;
    const float* bptr = bias;
    int n0 = blockIdx.x * 64;
    int mode_eff = mode;
    if (mode == 3) {
        if (blockIdx.x < 8) {
            mode_eff = 4;
        } else {
            bH = d_Wih_h; bL = d_Wih_l; ldb = G4;
            bptr = nullptr;
            n0 = (blockIdx.x - 8) * 64;
            mode_eff = 1;
        }
    }

    float acc[2][4][4];
#pragma unroll
    for (int i = 0; i < 2; i++)
#pragma unroll
        for (int j = 0; j < 4; j++)
#pragma unroll
            for (int q = 0; q < 4; q++) acc[i][j][q] = 0.f;

    const uint32_t a_row = wm * 32 + (lane & 15);
    const uint32_t a_k   = ((lane >> 4) & 1) * 8;
    const uint32_t b_row = wn * 32 + (lane & 7) + ((lane >> 4) & 1) * 8;
    const uint32_t b_k   = ((lane >> 3) & 1) * 8;

    auto load_stage = [&](int ic, int st) {
        const uint32_t stb = sb + st * STAGE_BYTES;
        const long long kc = (long long)ic * 64;
#pragma unroll
        for (int it = 0; it < 4; it++) {
            int idx = it * 256 + tid;
            int row = idx >> 3, k8 = (idx & 7) * 8;
            int m = m0 + row;
            bool p = (m < Mvalid);
            int mc = p ? m : (Mvalid - 1);
            uint32_t off = (row * ASTR + k8) * 2;
            cp16(stb + AH_OFF + off, &Ah[(size_t)mc * lda + kc + k8], p);
            cp16(stb + AL_OFF + off, &Al[(size_t)mc * lda + kc + k8], p);
        }
#pragma unroll
        for (int it = 0; it < 2; it++) {
            int idx = it * 256 + tid;
            int row = idx >> 3, k8 = (idx & 7) * 8;
            uint32_t off = (row * ASTR + k8) * 2;
            cp16(stb + BH_OFF + off, &bH[(size_t)(n0 + row) * ldb + kc + k8], true);
            cp16(stb + BL_OFF + off, &bL[(size_t)(n0 + row) * ldb + kc + k8], true);
        }
    };

    load_stage(0, 0);
    CP_COMMIT();

    for (int ic = 0; ic < chunks; ic++) {
        const int s = ic & 1;
        if (ic + 1 < chunks) load_stage(ic + 1, s ^ 1);
        CP_COMMIT();
        CP_WAIT1();
        __syncthreads();

        const uint32_t stb = sb + s * STAGE_BYTES;
#pragma unroll
        for (int ks = 0; ks < 4; ks++) {
            const uint32_t k16 = ks * 16;
            uint32_t ahf[2][4], alf[2][4], bhf[2][4], blf[2][4];
#pragma unroll
            for (int mt = 0; mt < 2; mt++) {
                uint32_t off = ((a_row + mt * 16) * ASTR + k16 + a_k) * 2;
                ldsm_x4(ahf[mt], stb + AH_OFF + off);
                ldsm_x4(alf[mt], stb + AL_OFF + off);
            }
#pragma unroll
            for (int np = 0; np < 2; np++) {
                uint32_t off = ((b_row + np * 16) * ASTR + k16 + b_k) * 2;
                ldsm_x4(bhf[np], stb + BH_OFF + off);
                ldsm_x4(blf[np], stb + BL_OFF + off);
            }
#pragma unroll
            for (int mt = 0; mt < 2; mt++)
#pragma unroll
                for (int np = 0; np < 2; np++) {
                    mma_bf16(acc[mt][np * 2 + 0], ahf[mt], &bhf[np][0]);
                    mma_bf16(acc[mt][np * 2 + 1], ahf[mt], &bhf[np][2]);
                    mma_bf16(acc[mt][np * 2 + 0], ahf[mt], &blf[np][0]);
                    mma_bf16(acc[mt][np * 2 + 1], ahf[mt], &blf[np][2]);
                    mma_bf16(acc[mt][np * 2 + 0], alf[mt], &bhf[np][0]);
                    mma_bf16(acc[mt][np * 2 + 1], alf[mt], &bhf[np][2]);
                }
        }
        __syncthreads();
    }

    const int g = lane >> 2, tg = lane & 3;
#pragma unroll
    for (int mt = 0; mt < 2; mt++) {
#pragma unroll
        for (int nt = 0; nt < 4; nt++) {
            int r0 = m0 + wm * 32 + mt * 16 + g;
            int c0 = n0 + wn * 32 + nt * 8 + tg * 2;
#pragma unroll
            for (int q = 0; q < 4; q++) {
                int m = r0 + (q >> 1) * 8;
                int n = c0 + (q & 1);
                if (m >= Mvalid) continue;
                float v = acc[mt][nt][q];
                if (mode_eff == 1) {
                    int nb = m >> 6, p = m & 63;
                    d_G[((size_t)nb * 2048 + n) * 64 + p] = __float2half(v);
                } else if (mode_eff == 4) {
                    d_attn_img[(size_t)m * ADIM + n] = __float2half(v + bptr[n]);
                } else if (mode_eff == 5) {
                    if (n < Nvalid) {
                        int gm = moff + m;          // global row, t-major
                        int tt = gm >> 6, nb = gm & 63;
                        C[(size_t)(nb * TSTEPS + tt) * ldc + n] = v + bptr[n];
                    }
                } else {
                    if (n < Nvalid) {
                        if (bptr) v += bptr[n];
                        C[(size_t)m * ldc + n] = v;
                    }
                }
            }
        }
    }
}

// =====================================================================
// Fused init GEMM: h0|c0 = F(64x98304) @ [Wh|Wc]; split-K 96.
// =====================================================================
#define IBSTR 136
#define IA_H 0
#define IA_L 9216
#define IB_H 18432
#define IB_L 35840
#define INIT_SMEM_BYTES 53248

__global__ void __launch_bounds__(256) init_mma(
    const float* __restrict__ Wh, const float* __restrict__ Wc,
    float* __restrict__ P)
{
    extern __shared__ char smem[];
    const uint32_t sb = smem_u32(smem);
    __nv_bfloat16* Bsh = (__nv_bfloat16*)(smem + IB_H);
    __nv_bfloat16* Bsl = (__nv_bfloat16*)(smem + IB_L);
    const int tid = threadIdx.x, lane = tid & 31, wid = tid >> 5;
    const int wm = wid >> 2, wn = wid & 3;
    const int bx = blockIdx.x;
    const float* __restrict__ W = (bx < 4) ? Wh : Wc;
    const int n0g = (bx & 3) * 128;
    const int outc0 = bx * 128;
    const size_t k0 = (size_t)blockIdx.y * 1024;

    float acc[2][4][4];
#pragma unroll
    for (int i = 0; i < 2; i++)
#pragma unroll
        for (int j = 0; j < 4; j++)
#pragma unroll
            for (int q = 0; q < 4; q++) acc[i][j][q] = 0.f;

    const uint32_t a_row = wm * 32 + (lane & 15);
    const uint32_t a_k   = ((lane >> 4) & 1) * 8;
    const uint32_t bt_k = ((lane >> 3) & 1) * 8 + (lane & 7);
    const uint32_t bt_n = ((lane >> 4) & 1) * 8;

    for (int ic = 0; ic < 16; ic++) {
        const size_t kg = k0 + ic * 64;
#pragma unroll
        for (int it = 0; it < 2; it++) {
            int idx = it * 256 + tid;
            int row = idx >> 3, k8 = (idx & 7) * 8;
            uint32_t off = (row * ASTR + k8) * 2;
            *(uint4*)(smem + IA_H + off) = *(const uint4*)&d_feat_h[(size_t)row * KINIT + kg + k8];
            *(uint4*)(smem + IA_L + off) = *(const uint4*)&d_feat_l[(size_t)row * KINIT + kg + k8];
        }
#pragma unroll
        for (int it = 0; it < 8; it++) {
            int idx = it * 256 + tid;
            int kk = idx >> 5, nn = (idx & 31) * 4;
            float4 v = *(const float4*)&W[(kg + kk) * 512 + n0g + nn];
            float a[4] = {v.x, v.y, v.z, v.w};
            __nv_bfloat16 h[4], l[4];
#pragma unroll
            for (int j = 0; j < 4; j++) {
                h[j] = __float2bfloat16(a[j]);
                l[j] = __float2bfloat16(a[j] - __bfloat162float(h[j]));
            }
            int o = kk * IBSTR + nn;
            *(__nv_bfloat162*)&Bsh[o]     = __halves2bfloat162(h[0], h[1]);
            *(__nv_bfloat162*)&Bsh[o + 2] = __halves2bfloat162(h[2], h[3]);
            *(__nv_bfloat162*)&Bsl[o]     = __halves2bfloat162(l[0], l[1]);
            *(__nv_bfloat162*)&Bsl[o + 2] = __halves2bfloat162(l[2], l[3]);
        }
        __syncthreads();

#pragma unroll
        for (int ks = 0; ks < 4; ks++) {
            const uint32_t k16 = ks * 16;
            uint32_t ahf[2][4], alf[2][4];
#pragma unroll
            for (int mt = 0; mt < 2; mt++) {
                uint32_t off = ((a_row + mt * 16) * ASTR + k16 + a_k) * 2;
                ldsm_x4(ahf[mt], sb + IA_H + off);
                ldsm_x4(alf[mt], sb + IA_L + off);
            }
#pragma unroll
            for (int ng = 0; ng < 2; ng++) {
                uint32_t bhf[4], blf[4];
                uint32_t off = ((k16 + bt_k) * IBSTR + wn * 32 + ng * 16 + bt_n) * 2;
                ldsm_x4_t(bhf, sb + IB_H + off);
                ldsm_x4_t(blf, sb + IB_L + off);
#pragma unroll
                for (int mt = 0; mt < 2; mt++) {
                    mma_bf16(acc[mt][ng * 2 + 0], ahf[mt], &bhf[0]);
                    mma_bf16(acc[mt][ng * 2 + 1], ahf[mt], &bhf[2]);
                    mma_bf16(acc[mt][ng * 2 + 0], ahf[mt], &blf[0]);
                    mma_bf16(acc[mt][ng * 2 + 1], ahf[mt], &blf[2]);
                    mma_bf16(acc[mt][ng * 2 + 0], alf[mt], &bhf[0]);
                    mma_bf16(acc[mt][ng * 2 + 1], alf[mt], &bhf[2]);
                }
            }
        }
        __syncthreads();
    }

    const int g = lane >> 2, tg = lane & 3;
    const int zb = blockIdx.y * 64;
#pragma unroll
    for (int mt = 0; mt < 2; mt++)
#pragma unroll
        for (int nt = 0; nt < 4; nt++) {
            int r0 = wm * 32 + mt * 16 + g;
            int c0 = outc0 + wn * 32 + nt * 8 + tg * 2;
#pragma unroll
            for (int q = 0; q < 4; q++) {
                int m = r0 + (q >> 1) * 8;
                int n = c0 + (q & 1);
                P[(size_t)(zb + m) * 1024 + n] = acc[mt][nt][q];
            }
        }
}

// deterministic reduce of NSPLIT split-K partials -> h0 (bf16 hi/lo), c0
__global__ void reduce_init(const float* __restrict__ P,
                            float* __restrict__ c)
{
    int r = blockIdx.x * 256 + threadIdx.x;   // 65536
    float s = 0.f;
#pragma unroll
    for (int j = 0; j < NSPLIT; j++) s += P[(size_t)j * 65536 + r];
    int m = r >> 10, col = r & 1023;
    if (col < 512) {
        __nv_bfloat16 hi = __float2bfloat16(s);
        d_hbf_h[m * 512 + col] = hi;
        d_hbf_l[m * 512 + col] = __float2bfloat16(s - __bfloat162float(hi));
    } else {
        c[m * 512 + col - 512] = s;
    }
}

// reset ordering counter (once per replay, before the loop)
__global__ void reset_ctr() { g_cP1 = 0u; }

// =====================================================================
// FUSED A+B KERNEL: small GEMMs + softmax in ONE launch per step.
// grid 224 x 256 threads, smem 69632 (3 CTAs/SM -> 444 slots >= 224,
// entire launch resident in wave 1 -> spin is deadlock-free).
//  blocks   0-159 : HMMA GEMM units (h @ [tokW;W_hh], split-K 4)
//  blocks 160-223 : softmax, spins until the 32 P1 producers signal.
// gates_lstm remains a separate full-width launch (graph edge sync).
// =====================================================================
#define SSTR 136
#define S_AH 0
#define S_AL 17408
#define S_BH 34816
#define S_BL 52224
#define STEP_SMEM 69632

__device__ __forceinline__ void spin_ge(volatile unsigned* p, unsigned target) {
    while (*p < target) { __nanosleep(64); }
}

__global__ void __launch_bounds__(256) smax_mma(
    const float* __restrict__ tb,
    const float* __restrict__ wfull,
    int t)
{
    extern __shared__ char smem[];
    const uint32_t sb = smem_u32(smem);
    const int tid = threadIdx.x, lane = tid & 31, wid = tid >> 5;
    const unsigned cta = blockIdx.x;

    if (cta < 160) {
        // ---------------- phase A: HMMA GEMM unit ----------------
        const int cb = cta >> 2, ks = cta & 3;
        const int k0 = ks * 128;
        float* __restrict__ P;
        int Ncols, cbl;
        if (cb < 8) { P = d_P1; Ncols = 512;  cbl = cb; }
        else        { P = d_P3; Ncols = 2048; cbl = cb - 8; }

#pragma unroll
        for (int it = 0; it < 4; it++) {           // 1024 uint4 / 256 thr
            int idx = it * 256 + tid;
            int row = idx >> 4, c8 = (idx & 15) * 8;
            uint32_t off = (row * SSTR + c8) * 2;
            *(uint4*)(smem + S_AH + off) = *(const uint4*)&d_hbf_h[row * 512 + k0 + c8];
            *(uint4*)(smem + S_AL + off) = *(const uint4*)&d_hbf_l[row * 512 + k0 + c8];
            *(uint4*)(smem + S_BH + off) = *(const uint4*)&d_sW_h[(size_t)(cb * 64 + row) * 512 + k0 + c8];
            *(uint4*)(smem + S_BL + off) = *(const uint4*)&d_sW_l[(size_t)(cb * 64 + row) * 512 + k0 + c8];
        }
        __syncthreads();

        if (wid < 4) {
            const int wm = wid >> 1, wn = wid & 1;
            float acc[2][4][4];
#pragma unroll
            for (int i = 0; i < 2; i++)
#pragma unroll
                for (int j = 0; j < 4; j++)
#pragma unroll
                    for (int q = 0; q < 4; q++) acc[i][j][q] = 0.f;

            const uint32_t a_row = wm * 32 + (lane & 15);
            const uint32_t a_k   = ((lane >> 4) & 1) * 8;
            const uint32_t b_row = wn * 32 + (lane & 7) + ((lane >> 4) & 1) * 8;
            const uint32_t b_k   = ((lane >> 3) & 1) * 8;

#pragma unroll
            for (int k16i = 0; k16i < 8; k16i++) {
                const uint32_t k16 = k16i * 16;
                uint32_t ahf[2][4], alf[2][4], bhf[2][4], blf[2][4];
#pragma unroll
                for (int mt = 0; mt < 2; mt++) {
                    uint32_t off = ((a_row + mt * 16) * SSTR + k16 + a_k) * 2;
                    ldsm_x4(ahf[mt], sb + S_AH + off);
                    ldsm_x4(alf[mt], sb + S_AL + off);
                }
#pragma unroll
                for (int np = 0; np < 2; np++) {
                    uint32_t off = ((b_row + np * 16) * SSTR + k16 + b_k) * 2;
                    ldsm_x4(bhf[np], sb + S_BH + off);
                    ldsm_x4(blf[np], sb + S_BL + off);
                }
#pragma unroll
                for (int mt = 0; mt < 2; mt++)
#pragma unroll
                    for (int np = 0; np < 2; np++) {
                        mma_bf16(acc[mt][np * 2 + 0], ahf[mt], &bhf[np][0]);
                        mma_bf16(acc[mt][np * 2 + 1], ahf[mt], &bhf[np][2]);
                        mma_bf16(acc[mt][np * 2 + 0], ahf[mt], &blf[np][0]);
                        mma_bf16(acc[mt][np * 2 + 1], ahf[mt], &blf[np][2]);
                        mma_bf16(acc[mt][np * 2 + 0], alf[mt], &bhf[np][0]);
                        mma_bf16(acc[mt][np * 2 + 1], alf[mt], &bhf[np][2]);
                    }
            }

            const int g = lane >> 2, tg = lane & 3;
#pragma unroll
            for (int mt = 0; mt < 2; mt++)
#pragma unroll
                for (int nt = 0; nt < 4; nt++) {
                    int r0 = wm * 32 + mt * 16 + g;
                    int c0 = cbl * 64 + wn * 32 + nt * 8 + tg * 2;
#pragma unroll
                    for (int q = 0; q < 4; q++) {
                        int m = r0 + (q >> 1) * 8;
                        int n = c0 + (q & 1);
                        P[(size_t)(ks * 64 + m) * Ncols + n] = acc[mt][nt][q];
                    }
                }
        }
        if (cb < 8) {
            __threadfence();
            __syncthreads();
            if (tid == 0) atomicAdd(&g_cP1, 1u);
        }

    } else {
        // ---------------- phase B: softmax (spins on 32 P1 producers) ----
        const int n = cta - 160;
        float* ah = (float*)smem;        // 512
        float* wf = ah + 512;            // 512
        float* sc = wf + 512;            // 64

        if (tid == 0) spin_ge(&g_cP1, (unsigned)(t + 1) * 32u);
        __syncthreads();

#pragma unroll
        for (int half = 0; half < 2; half++) {
            int a = half * 256 + tid;
            float v = tb[a];
#pragma unroll
            for (int s = 0; s < 4; s++)
                v += __ldcg(&d_P1[(size_t)(s * 64 + n) * 512 + a]);
            ah[a] = v;
            wf[a] = wfull[a];
        }
        __syncthreads();

        const int warp = tid >> 5;       // 8 warps
        for (int p = warp; p < 64; p += 8) {
            const __half* img = &d_attn_img[(size_t)(n * 64 + p) * 512];
            float s = 0.f;
#pragma unroll
            for (int a = lane; a < 512; a += 32) {
                float e = ah[a] + __half2float(img[a]);
                if (e > 0.f) s += e * wf[a];
            }
#pragma unroll
            for (int o = 16; o > 0; o >>= 1) s += __shfl_xor_sync(0xFFFFFFFFu, s, o);
            if (lane == 0) sc[p] = s;
        }
        __syncthreads();
        if (tid < 32) {
            float s0 = sc[tid], s1 = sc[tid + 32];
            float mx = fmaxf(s0, s1);
#pragma unroll
            for (int o = 16; o > 0; o >>= 1) mx = fmaxf(mx, __shfl_xor_sync(0xFFFFFFFFu, mx, o));
            float e0 = expf(s0 - mx), e1 = expf(s1 - mx);
            float sum = e0 + e1;
#pragma unroll
            for (int o = 16; o > 0; o >>= 1) sum += __shfl_xor_sync(0xFFFFFFFFu, sum, o);
            float inv = 1.f / sum;
            d_logits[n * 64 + tid]      = e0 * inv;
            d_logits[n * 64 + tid + 32] = e1 * inv;
        }
    }
}

// =====================================================================
// Gates assembly + LSTM pointwise (G fp16); h out t-major for FC.
// grid (64 n, 8 hchunk), 256 threads. Separate launch (graph-edge sync).
// =====================================================================
__global__ void gates_lstm(const float* __restrict__ P3,
                           const float* __restrict__ pre_t,
                           const float* __restrict__ b_ih,
                           const float* __restrict__ b_hh,
                           int t)
{
    const int n = blockIdx.x, hc = blockIdx.y, tid = threadIdx.x;
    __shared__ float lg[64];
    __shared__ float sg[4][64];
    if (tid < 64) lg[tid] = d_logits[n * 64 + tid];
    __syncthreads();

    const int q = tid >> 6, hl = tid & 63;
    const int j = q * 512 + hc * 64 + hl;
    float acc = b_ih[j] + b_hh[j] + pre_t[n * 2048 + j];
#pragma unroll
    for (int s = 0; s < 4; s++) acc += P3[(size_t)(s * 64 + n) * 2048 + j];
    const uint4* g4 = (const uint4*)&d_G[((size_t)n * 2048 + j) * 64];
#pragma unroll
    for (int pi = 0; pi < 8; pi++) {
        uint4 u = g4[pi];
        __half2 h0 = *(__half2*)&u.x, h1 = *(__half2*)&u.y;
        __half2 h2 = *(__half2*)&u.z, h3 = *(__half2*)&u.w;
        float2 f0 = __half22float2(h0), f1 = __half22float2(h1);
        float2 f2 = __half22float2(h2), f3 = __half22float2(h3);
        const float* w = &lg[pi * 8];
        acc += w[0] * f0.x + w[1] * f0.y + w[2] * f1.x + w[3] * f1.y
             + w[4] * f2.x + w[5] * f2.y + w[6] * f3.x + w[7] * f3.y;
    }
    sg[q][hl] = acc;
    __syncthreads();

    if (tid < 64) {
        int hidx = hc * 64 + tid;
        float ig = sg[0][tid], fg = sg[1][tid], gg = sg[2][tid], og = sg[3][tid];
        float si = 1.f / (1.f + expf(-ig));
        float sf = 1.f / (1.f + expf(-fg));
        float so = 1.f / (1.f + expf(-og));
        float cn = sf * d_c[n * 512 + hidx] + si * tanhf(gg);
        float hn = so * tanhf(cn);
        d_c[n * 512 + hidx] = cn;
        __nv_bfloat16 hi = __float2bfloat16(hn);
        __nv_bfloat16 lo = __float2bfloat16(hn - __bfloat162float(hi));
        d_hbf_h[n * 512 + hidx] = hi;
        d_hbf_l[n * 512 + hidx] = lo;
        size_t o = ((size_t)t * NBATCH + n) * 512 + hidx;   // t-major
        d_houtbf_h[o] = hi;
        d_houtbf_l[o] = lo;
    }
}

// =====================================================================
// Host side
// =====================================================================
template <typename Tp>
static void* symaddr(Tp& ref)
{
    void* p = nullptr;
    cudaGetSymbolAddress(&p, ref);
    return p;
}

extern "C" void kernel_launch(void* const* d_in, const int* in_sizes, int n_in,
                              void* d_out, int out_size)
{
    const float* features     = (const float*)d_in[0];
    const int*   captions     = (const int*)  d_in[1];
    const float* embd_W       = (const float*)d_in[2];
    const float* attn_token_W = (const float*)d_in[3];
    const float* attn_token_b = (const float*)d_in[4];
    const float* attn_feat_W  = (const float*)d_in[5];
    const float* attn_feat_b  = (const float*)d_in[6];
    const float* attn_full_W  = (const float*)d_in[7];
    // d_in[8] attn_full_b: softmax-invariant constant -> skipped
    const float* W_ih         = (const float*)d_in[9];
    const float* b_ih         = (const float*)d_in[10];
    const float* W_hh         = (const float*)d_in[11];
    const float* b_hh         = (const float*)d_in[12];
    const float* fc_W         = (const float*)d_in[13];
    const float* fc_b         = (const float*)d_in[14];
    const float* init_Wh      = (const float*)d_in[15];
    const float* init_Wc      = (const float*)d_in[16];
    float* out = (float*)d_out;

    __nv_bfloat16* p_feat_h = (__nv_bfloat16*)symaddr(d_feat_h);
    __nv_bfloat16* p_feat_l = (__nv_bfloat16*)symaddr(d_feat_l);
    __nv_bfloat16* p_Wih_h  = (__nv_bfloat16*)symaddr(d_Wih_h);
    __nv_bfloat16* p_Wih_l  = (__nv_bfloat16*)symaddr(d_Wih_l);
    __nv_bfloat16* p_afW_h  = (__nv_bfloat16*)symaddr(d_afW_h);
    __nv_bfloat16* p_afW_l  = (__nv_bfloat16*)symaddr(d_afW_l);
    __nv_bfloat16* p_fcW_h  = (__nv_bfloat16*)symaddr(d_fcW_h);
    __nv_bfloat16* p_fcW_l  = (__nv_bfloat16*)symaddr(d_fcW_l);
    __nv_bfloat16* p_emb_h  = (__nv_bfloat16*)symaddr(d_embbf_h);
    __nv_bfloat16* p_emb_l  = (__nv_bfloat16*)symaddr(d_embbf_l);
    __nv_bfloat16* p_hbf_h  = (__nv_bfloat16*)symaddr(d_houtbf_h);
    __nv_bfloat16* p_hbf_l  = (__nv_bfloat16*)symaddr(d_houtbf_l);

    float* p_pre  = (float*)symaddr(d_pre);
    float* p_part = (float*)symaddr(d_part);
    float* p_c    = (float*)symaddr(d_c);
    float* p_P3   = (float*)symaddr(d_P3);

    // opt-in to >48KB dynamic smem (idempotent)
    cudaFuncAttributes fa;
    cudaFuncGetAttributes(&fa, mma_nt);
    if (fa.maxDynamicSharedSizeBytes < MMA_SMEM_BYTES)
        cudaFuncSetAttribute(mma_nt, cudaFuncAttributeMaxDynamicSharedMemorySize,
                             MMA_SMEM_BYTES);
    cudaFuncGetAttributes(&fa, init_mma);
    if (fa.maxDynamicSharedSizeBytes < INIT_SMEM_BYTES)
        cudaFuncSetAttribute(init_mma, cudaFuncAttributeMaxDynamicSharedMemorySize,
                             INIT_SMEM_BYTES);
    cudaFuncGetAttributes(&fa, smax_mma);
    if (fa.maxDynamicSharedSizeBytes < STEP_SMEM)
        cudaFuncSetAttribute(smax_mma, cudaFuncAttributeMaxDynamicSharedMemorySize,
                             STEP_SMEM);

    // side stream + events (host-side objects only)
    static cudaStream_t s2 = nullptr;
    static cudaEvent_t evA = nullptr, evB = nullptr;
    if (!s2) {
        cudaStreamCreateWithFlags(&s2, cudaStreamNonBlocking);
        cudaEventCreateWithFlags(&evA, cudaEventDisableTiming);
        cudaEventCreateWithFlags(&evB, cudaEventDisableTiming);
    }

    // ---- conversions (stream 0) ----
    cvt_all<<<17312, 256>>>(features, W_ih, attn_feat_W, fc_W,
                            attn_token_W, W_hh);
    cudaEventRecord(evA, 0);

    // ---- fork: init GEMM chain on s2 ----
    cudaStreamWaitEvent(s2, evA, 0);
    init_mma<<<dim3(8, NSPLIT), 256, INIT_SMEM_BYTES, s2>>>(init_Wh, init_Wc, p_part);
    reduce_init<<<256, 256, 0, s2>>>(p_part, p_c);
    cudaEventRecord(evB, s2);

    // ---- stream 0: remaining prologue ----
    emb_gather_bf<<<TSTEPS * NBATCH, 128>>>(captions, embd_W, p_emb_h, p_emb_l);
    reset_ctr<<<1, 1>>>();
    // pre_emb = emb @ W_ih[:,1536:]^T  (2048 x 2048, K=512)
    mma_nt<<<dim3(32, 16, 1), 256, MMA_SMEM_BYTES>>>(
        p_emb_h, p_emb_l, EMBD, TSTEPS * NBATCH, p_Wih_h + 1536, p_Wih_l + 1536, G4,
        p_pre, G4, G4, 8, nullptr, 0, 0);
    // merged: attn_img (fp16) + G (fp16)
    mma_nt<<<dim3(40, 32, 1), 256, MMA_SMEM_BYTES>>>(
        p_feat_h, p_feat_l, ENCC, MROWS, p_afW_h, p_afW_l, ENCC,
        nullptr, ADIM, ADIM, 24, attn_feat_b, 3, 0);

    // ---- join: h0/c0 ready before the recurrence ----
    cudaStreamWaitEvent((cudaStream_t)0, evB, 0);

    // ---- sequential recurrence: 2 launches per step ----
    for (int t = 0; t < TSTEPS; ++t) {
        smax_mma<<<224, 256, STEP_SMEM>>>(attn_token_b, attn_full_W, t);
        gates_lstm<<<dim3(64, 8), 256>>>(p_P3, p_pre + (size_t)t * NBATCH * G4,
                                         b_ih, b_hh, t);
    }

    // ---- epilogue: FC over all timesteps (t-major rows, mode 5) ----
    mma_nt<<<dim3(157, 16, 1), 256, MMA_SMEM_BYTES>>>(
        p_hbf_h, p_hbf_l, HDIM, TSTEPS * NBATCH, p_fcW_h, p_fcW_l, HDIM,
        out, VOCAB, VOCAB, 8, fc_b, 5, 0);
}

// round 16
// speedup vs baseline: 1.1512x; 1.0218x over previous
#include <cuda_runtime.h>
#include <cuda_bf16.h>
#include <cuda_fp16.h>
#include <cstdint>
#include <math.h>

// ---------------- problem constants ----------------
#define TSTEPS 32
#define NBATCH 64
#define NPIX   64
#define ENCC   1536
#define EMBD   512
#define ADIM   512
#define HDIM   512
#define G4     2048     // 4*H
#define VOCAB  10000
#define VPAD   10048    // 157*64
#define MROWS  4096     // N*P
#define KINIT  98304    // P*ENC
#define NSPLIT 96       // init split-K

// ---------------- scratch (__device__ globals; no allocation) ----------------
__device__ __align__(16) __nv_bfloat16 d_feat_h[MROWS * ENCC];
__device__ __align__(16) __nv_bfloat16 d_feat_l[MROWS * ENCC];
__device__ __align__(16) __nv_bfloat16 d_Wih_h[G4 * G4];
__device__ __align__(16) __nv_bfloat16 d_Wih_l[G4 * G4];
__device__ __align__(16) __nv_bfloat16 d_afW_h[ADIM * ENCC];
__device__ __align__(16) __nv_bfloat16 d_afW_l[ADIM * ENCC];
__device__ __align__(16) __nv_bfloat16 d_fcW_h[VPAD * HDIM];
__device__ __align__(16) __nv_bfloat16 d_fcW_l[VPAD * HDIM];
__device__ __align__(16) __nv_bfloat16 d_embbf_h[TSTEPS * NBATCH * EMBD];
__device__ __align__(16) __nv_bfloat16 d_embbf_l[TSTEPS * NBATCH * EMBD];
// t-major hidden outputs: [t*64+n][512]
__device__ __align__(16) __nv_bfloat16 d_houtbf_h[TSTEPS * NBATCH * HDIM];
__device__ __align__(16) __nv_bfloat16 d_houtbf_l[TSTEPS * NBATCH * HDIM];
// stacked small-GEMM weights: rows 0-511 attn_token_W, rows 512-2559 W_hh
__device__ __align__(16) __nv_bfloat16 d_sW_h[2560 * 512];
__device__ __align__(16) __nv_bfloat16 d_sW_l[2560 * 512];
// per-step h in bf16 hi/lo
__device__ __align__(16) __nv_bfloat16 d_hbf_h[NBATCH * HDIM];
__device__ __align__(16) __nv_bfloat16 d_hbf_l[NBATCH * HDIM];

__device__ __align__(16) __half d_attn_img[MROWS * ADIM];            // fp16, 4 MB
__device__ __align__(16) __half d_G[(size_t)NBATCH * G4 * NPIX];     // fp16, 16.7 MB
__device__ float d_pre[TSTEPS * NBATCH * G4];
__device__ float d_part[NSPLIT * 64 * 1024];       // init split-K partials (25MB)
__device__ float d_c[NBATCH * HDIM];
__device__ float d_P1[4 * NBATCH * ADIM];
__device__ float d_P3[4 * NBATCH * G4];
__device__ float d_logits[NBATCH * NPIX];

// =====================================================================
// warp-MMA + cp.async helpers (sm_80+ PTX, no arch-feature gating)
// =====================================================================
__device__ __forceinline__ uint32_t smem_u32(const void* p) {
    uint32_t a;
    asm("{ .reg .u64 t; cvta.to.shared.u64 t, %1; cvt.u32.u64 %0, t; }" : "=r"(a) : "l"(p));
    return a;
}
__device__ __forceinline__ void ldsm_x4(uint32_t* r, uint32_t addr) {
    asm volatile("ldmatrix.sync.aligned.m8n8.x4.shared.b16 {%0,%1,%2,%3}, [%4];"
                 : "=r"(r[0]), "=r"(r[1]), "=r"(r[2]), "=r"(r[3]) : "r"(addr));
}
__device__ __forceinline__ void ldsm_x4_t(uint32_t* r, uint32_t addr) {
    asm volatile("ldmatrix.sync.aligned.m8n8.x4.trans.shared.b16 {%0,%1,%2,%3}, [%4];"
                 : "=r"(r[0]), "=r"(r[1]), "=r"(r[2]), "=r"(r[3]) : "r"(addr));
}
__device__ __forceinline__ void mma_bf16(float* c, const uint32_t* a, const uint32_t* b) {
    asm volatile(
        "mma.sync.aligned.m16n8k16.row.col.f32.bf16.bf16.f32 "
        "{%0,%1,%2,%3}, {%4,%5,%6,%7}, {%8,%9}, {%0,%1,%2,%3};"
        : "+f"(c[0]), "+f"(c[1]), "+f"(c[2]), "+f"(c[3])
        : "r"(a[0]), "r"(a[1]), "r"(a[2]), "r"(a[3]), "r"(b[0]), "r"(b[1]));
}
__device__ __forceinline__ void cp16(uint32_t dst, const void* src, bool pred) {
    int sz = pred ? 16 : 0;
    asm volatile("cp.async.cg.shared.global [%0], [%1], 16, %2;"
                 :: "r"(dst), "l"(src), "r"(sz) : "memory");
}
#define CP_COMMIT() asm volatile("cp.async.commit_group;" ::: "memory")
#define CP_WAIT1()  asm volatile("cp.async.wait_group 1;" ::: "memory")

// =====================================================================
// Fused fp32 -> bf16 hi/lo conversion (6 segments).
// =====================================================================
__global__ void cvt_all(const float* __restrict__ feat,
                        const float* __restrict__ Wih,
                        const float* __restrict__ afW,
                        const float* __restrict__ fcW,
                        const float* __restrict__ tokW,
                        const float* __restrict__ Whh)
{
    int b = blockIdx.x;
    const float* src;
    __nv_bfloat16 *dh, *dl;
    int n_src, lb;
    if (b < 6144)       { src = feat; dh = d_feat_h; dl = d_feat_l; n_src = MROWS * ENCC; lb = b; }
    else if (b < 10240) { src = Wih;  dh = d_Wih_h;  dl = d_Wih_l;  n_src = G4 * G4;      lb = b - 6144; }
    else if (b < 11008) { src = afW;  dh = d_afW_h;  dl = d_afW_l;  n_src = ADIM * ENCC;  lb = b - 10240; }
    else if (b < 16032) { src = fcW;  dh = d_fcW_h;  dl = d_fcW_l;  n_src = VOCAB * HDIM; lb = b - 11008; }
    else if (b < 16288) { src = tokW; dh = d_sW_h;   dl = d_sW_l;   n_src = 512 * 512;    lb = b - 16032; }
    else                { src = Whh;  dh = d_sW_h + 262144; dl = d_sW_l + 262144;
                          n_src = 2048 * 512; lb = b - 16288; }
    int i = (lb * 256 + threadIdx.x) * 4;
    float4 v = make_float4(0.f, 0.f, 0.f, 0.f);
    if (i < n_src) v = *(const float4*)&src[i];
    float a[4] = {v.x, v.y, v.z, v.w};
    __nv_bfloat16 h[4], l[4];
#pragma unroll
    for (int j = 0; j < 4; j++) {
        h[j] = __float2bfloat16(a[j]);
        l[j] = __float2bfloat16(a[j] - __bfloat162float(h[j]));
    }
    *(__nv_bfloat162*)&dh[i]     = __halves2bfloat162(h[0], h[1]);
    *(__nv_bfloat162*)&dh[i + 2] = __halves2bfloat162(h[2], h[3]);
    *(__nv_bfloat162*)&dl[i]     = __halves2bfloat162(l[0], l[1]);
    *(__nv_bfloat162*)&dl[i + 2] = __halves2bfloat162(l[2], l[3]);
}

// embedding gather straight into bf16 hi/lo [t*64+n][e]
__global__ void emb_gather_bf(const int* __restrict__ cap,
                              const float* __restrict__ EW,
                              __nv_bfloat16* __restrict__ dh,
                              __nv_bfloat16* __restrict__ dl)
{
    int m = blockIdx.x;                 // t*64+n
    int n = m & 63, t = m >> 6;
    int tok = cap[n * TSTEPS + t];
    int i = threadIdx.x * 4;            // 128 thr * 4 = 512
    float4 v = *(const float4*)&EW[(size_t)tok * EMBD + i];
    float a[4] = {v.x, v.y, v.z, v.w};
    __nv_bfloat16 h[4], l[4];
#pragma unroll
    for (int j = 0; j < 4; j++) {
        h[j] = __float2bfloat16(a[j]);
        l[j] = __float2bfloat16(a[j] - __bfloat162float(h[j]));
    }
    size_t o = (size_t)m * EMBD + i;
    *(__nv_bfloat162*)&dh[o]     = __halves2bfloat162(h[0], h[1]);
    *(__nv_bfloat162*)&dh[o + 2] = __halves2bfloat162(h[2], h[3]);
    *(__nv_bfloat162*)&dl[o]     = __halves2bfloat162(l[0], l[1]);
    *(__nv_bfloat162*)&dl[o + 2] = __halves2bfloat162(l[2], l[3]);
}

// =====================================================================
// Warp-MMA NT GEMM, bf16 hi/lo split, fp32 accumulate, cp.async 2-stage.
// mode 0: fp32 C[m*ldc+n] (+bias)
// mode 3: merged — blockIdx.x<8: attn_img fp16 (+bias); else G fp16 layout
// mode 5: FC — A rows t-major (global row = moff+m), store [n][t][v] +bias
// =====================================================================
#define ASTR 72
#define AH_OFF 0
#define AL_OFF 18432
#define BH_OFF 36864
#define BL_OFF 46080
#define STAGE_BYTES 55296
#define MMA_SMEM_BYTES (2 * STAGE_BYTES)

__global__ void __launch_bounds__(256) mma_nt(
    const __nv_bfloat16* __restrict__ Ah, const __nv_bfloat16* __restrict__ Al,
    int lda, int Mvalid,
    const __nv_bfloat16* __restrict__ Bh, const __nv_bfloat16* __restrict__ Bl,
    int ldb,
    float* __restrict__ C, int Nvalid, int ldc,
    int chunks, const float* __restrict__ bias, int mode, int moff)
{
    extern __shared__ char smem[];
    const uint32_t sb = smem_u32(smem);
    const int tid = threadIdx.x, lane = tid & 31, wid = tid >> 5;
    const int wm = wid >> 1, wn = wid & 1;
    const int m0 = blockIdx.y * 128;

    const __nv_bfloat16* bH = Bh;
    const __nv_bfloat16* bL = Bl;
    const float* bptr = bias;
    int n0 = blockIdx.x * 64;
    int mode_eff = mode;
    if (mode == 3) {
        if (blockIdx.x < 8) {
            mode_eff = 4;
        } else {
            bH = d_Wih_h; bL = d_Wih_l; ldb = G4;
            bptr = nullptr;
            n0 = (blockIdx.x - 8) * 64;
            mode_eff = 1;
        }
    }

    float acc[2][4][4];
#pragma unroll
    for (int i = 0; i < 2; i++)
#pragma unroll
        for (int j = 0; j < 4; j++)
#pragma unroll
            for (int q = 0; q < 4; q++) acc[i][j][q] = 0.f;

    const uint32_t a_row = wm * 32 + (lane & 15);
    const uint32_t a_k   = ((lane >> 4) & 1) * 8;
    const uint32_t b_row = wn * 32 + (lane & 7) + ((lane >> 4) & 1) * 8;
    const uint32_t b_k   = ((lane >> 3) & 1) * 8;

    auto load_stage = [&](int ic, int st) {
        const uint32_t stb = sb + st * STAGE_BYTES;
        const long long kc = (long long)ic * 64;
#pragma unroll
        for (int it = 0; it < 4; it++) {
            int idx = it * 256 + tid;
            int row = idx >> 3, k8 = (idx & 7) * 8;
            int m = m0 + row;
            bool p = (m < Mvalid);
            int mc = p ? m : (Mvalid - 1);
            uint32_t off = (row * ASTR + k8) * 2;
            cp16(stb + AH_OFF + off, &Ah[(size_t)mc * lda + kc + k8], p);
            cp16(stb + AL_OFF + off, &Al[(size_t)mc * lda + kc + k8], p);
        }
#pragma unroll
        for (int it = 0; it < 2; it++) {
            int idx = it * 256 + tid;
            int row = idx >> 3, k8 = (idx & 7) * 8;
            uint32_t off = (row * ASTR + k8) * 2;
            cp16(stb + BH_OFF + off, &bH[(size_t)(n0 + row) * ldb + kc + k8], true);
            cp16(stb + BL_OFF + off, &bL[(size_t)(n0 + row) * ldb + kc + k8], true);
        }
    };

    load_stage(0, 0);
    CP_COMMIT();

    for (int ic = 0; ic < chunks; ic++) {
        const int s = ic & 1;
        if (ic + 1 < chunks) load_stage(ic + 1, s ^ 1);
        CP_COMMIT();
        CP_WAIT1();
        __syncthreads();

        const uint32_t stb = sb + s * STAGE_BYTES;
#pragma unroll
        for (int ks = 0; ks < 4; ks++) {
            const uint32_t k16 = ks * 16;
            uint32_t ahf[2][4], alf[2][4], bhf[2][4], blf[2][4];
#pragma unroll
            for (int mt = 0; mt < 2; mt++) {
                uint32_t off = ((a_row + mt * 16) * ASTR + k16 + a_k) * 2;
                ldsm_x4(ahf[mt], stb + AH_OFF + off);
                ldsm_x4(alf[mt], stb + AL_OFF + off);
            }
#pragma unroll
            for (int np = 0; np < 2; np++) {
                uint32_t off = ((b_row + np * 16) * ASTR + k16 + b_k) * 2;
                ldsm_x4(bhf[np], stb + BH_OFF + off);
                ldsm_x4(blf[np], stb + BL_OFF + off);
            }
#pragma unroll
            for (int mt = 0; mt < 2; mt++)
#pragma unroll
                for (int np = 0; np < 2; np++) {
                    mma_bf16(acc[mt][np * 2 + 0], ahf[mt], &bhf[np][0]);
                    mma_bf16(acc[mt][np * 2 + 1], ahf[mt], &bhf[np][2]);
                    mma_bf16(acc[mt][np * 2 + 0], ahf[mt], &blf[np][0]);
                    mma_bf16(acc[mt][np * 2 + 1], ahf[mt], &blf[np][2]);
                    mma_bf16(acc[mt][np * 2 + 0], alf[mt], &bhf[np][0]);
                    mma_bf16(acc[mt][np * 2 + 1], alf[mt], &bhf[np][2]);
                }
        }
        __syncthreads();
    }

    const int g = lane >> 2, tg = lane & 3;
#pragma unroll
    for (int mt = 0; mt < 2; mt++) {
#pragma unroll
        for (int nt = 0; nt < 4; nt++) {
            int r0 = m0 + wm * 32 + mt * 16 + g;
            int c0 = n0 + wn * 32 + nt * 8 + tg * 2;
#pragma unroll
            for (int q = 0; q < 4; q++) {
                int m = r0 + (q >> 1) * 8;
                int n = c0 + (q & 1);
                if (m >= Mvalid) continue;
                float v = acc[mt][nt][q];
                if (mode_eff == 1) {
                    int nb = m >> 6, p = m & 63;
                    d_G[((size_t)nb * 2048 + n) * 64 + p] = __float2half(v);
                } else if (mode_eff == 4) {
                    d_attn_img[(size_t)m * ADIM + n] = __float2half(v + bptr[n]);
                } else if (mode_eff == 5) {
                    if (n < Nvalid) {
                        int gm = moff + m;          // global row, t-major
                        int tt = gm >> 6, nb = gm & 63;
                        C[(size_t)(nb * TSTEPS + tt) * ldc + n] = v + bptr[n];
                    }
                } else {
                    if (n < Nvalid) {
                        if (bptr) v += bptr[n];
                        C[(size_t)m * ldc + n] = v;
                    }
                }
            }
        }
    }
}

// =====================================================================
// Fused init GEMM: h0|c0 = F(64x98304) @ [Wh|Wc]; split-K 96.
// =====================================================================
#define IBSTR 136
#define IA_H 0
#define IA_L 9216
#define IB_H 18432
#define IB_L 35840
#define INIT_SMEM_BYTES 53248

__global__ void __launch_bounds__(256) init_mma(
    const float* __restrict__ Wh, const float* __restrict__ Wc,
    float* __restrict__ P)
{
    extern __shared__ char smem[];
    const uint32_t sb = smem_u32(smem);
    __nv_bfloat16* Bsh = (__nv_bfloat16*)(smem + IB_H);
    __nv_bfloat16* Bsl = (__nv_bfloat16*)(smem + IB_L);
    const int tid = threadIdx.x, lane = tid & 31, wid = tid >> 5;
    const int wm = wid >> 2, wn = wid & 3;
    const int bx = blockIdx.x;
    const float* __restrict__ W = (bx < 4) ? Wh : Wc;
    const int n0g = (bx & 3) * 128;
    const int outc0 = bx * 128;
    const size_t k0 = (size_t)blockIdx.y * 1024;

    float acc[2][4][4];
#pragma unroll
    for (int i = 0; i < 2; i++)
#pragma unroll
        for (int j = 0; j < 4; j++)
#pragma unroll
            for (int q = 0; q < 4; q++) acc[i][j][q] = 0.f;

    const uint32_t a_row = wm * 32 + (lane & 15);
    const uint32_t a_k   = ((lane >> 4) & 1) * 8;
    const uint32_t bt_k = ((lane >> 3) & 1) * 8 + (lane & 7);
    const uint32_t bt_n = ((lane >> 4) & 1) * 8;

    for (int ic = 0; ic < 16; ic++) {
        const size_t kg = k0 + ic * 64;
#pragma unroll
        for (int it = 0; it < 2; it++) {
            int idx = it * 256 + tid;
            int row = idx >> 3, k8 = (idx & 7) * 8;
            uint32_t off = (row * ASTR + k8) * 2;
            *(uint4*)(smem + IA_H + off) = *(const uint4*)&d_feat_h[(size_t)row * KINIT + kg + k8];
            *(uint4*)(smem + IA_L + off) = *(const uint4*)&d_feat_l[(size_t)row * KINIT + kg + k8];
        }
#pragma unroll
        for (int it = 0; it < 8; it++) {
            int idx = it * 256 + tid;
            int kk = idx >> 5, nn = (idx & 31) * 4;
            float4 v = *(const float4*)&W[(kg + kk) * 512 + n0g + nn];
            float a[4] = {v.x, v.y, v.z, v.w};
            __nv_bfloat16 h[4], l[4];
#pragma unroll
            for (int j = 0; j < 4; j++) {
                h[j] = __float2bfloat16(a[j]);
                l[j] = __float2bfloat16(a[j] - __bfloat162float(h[j]));
            }
            int o = kk * IBSTR + nn;
            *(__nv_bfloat162*)&Bsh[o]     = __halves2bfloat162(h[0], h[1]);
            *(__nv_bfloat162*)&Bsh[o + 2] = __halves2bfloat162(h[2], h[3]);
            *(__nv_bfloat162*)&Bsl[o]     = __halves2bfloat162(l[0], l[1]);
            *(__nv_bfloat162*)&Bsl[o + 2] = __halves2bfloat162(l[2], l[3]);
        }
        __syncthreads();

#pragma unroll
        for (int ks = 0; ks < 4; ks++) {
            const uint32_t k16 = ks * 16;
            uint32_t ahf[2][4], alf[2][4];
#pragma unroll
            for (int mt = 0; mt < 2; mt++) {
                uint32_t off = ((a_row + mt * 16) * ASTR + k16 + a_k) * 2;
                ldsm_x4(ahf[mt], sb + IA_H + off);
                ldsm_x4(alf[mt], sb + IA_L + off);
            }
#pragma unroll
            for (int ng = 0; ng < 2; ng++) {
                uint32_t bhf[4], blf[4];
                uint32_t off = ((k16 + bt_k) * IBSTR + wn * 32 + ng * 16 + bt_n) * 2;
                ldsm_x4_t(bhf, sb + IB_H + off);
                ldsm_x4_t(blf, sb + IB_L + off);
#pragma unroll
                for (int mt = 0; mt < 2; mt++) {
                    mma_bf16(acc[mt][ng * 2 + 0], ahf[mt], &bhf[0]);
                    mma_bf16(acc[mt][ng * 2 + 1], ahf[mt], &bhf[2]);
                    mma_bf16(acc[mt][ng * 2 + 0], ahf[mt], &blf[0]);
                    mma_bf16(acc[mt][ng * 2 + 1], ahf[mt], &blf[2]);
                    mma_bf16(acc[mt][ng * 2 + 0], alf[mt], &bhf[0]);
                    mma_bf16(acc[mt][ng * 2 + 1], alf[mt], &bhf[2]);
                }
            }
        }
        __syncthreads();
    }

    const int g = lane >> 2, tg = lane & 3;
    const int zb = blockIdx.y * 64;
#pragma unroll
    for (int mt = 0; mt < 2; mt++)
#pragma unroll
        for (int nt = 0; nt < 4; nt++) {
            int r0 = wm * 32 + mt * 16 + g;
            int c0 = outc0 + wn * 32 + nt * 8 + tg * 2;
#pragma unroll
            for (int q = 0; q < 4; q++) {
                int m = r0 + (q >> 1) * 8;
                int n = c0 + (q & 1);
                P[(size_t)(zb + m) * 1024 + n] = acc[mt][nt][q];
            }
        }
}

// deterministic reduce of NSPLIT split-K partials -> h0 (bf16 hi/lo), c0
__global__ void reduce_init(const float* __restrict__ P,
                            float* __restrict__ c)
{
    int r = blockIdx.x * 256 + threadIdx.x;   // 65536
    float s = 0.f;
#pragma unroll
    for (int j = 0; j < NSPLIT; j++) s += P[(size_t)j * 65536 + r];
    int m = r >> 10, col = r & 1023;
    if (col < 512) {
        __nv_bfloat16 hi = __float2bfloat16(s);
        d_hbf_h[m * 512 + col] = hi;
        d_hbf_l[m * 512 + col] = __float2bfloat16(s - __bfloat162float(hi));
    } else {
        c[m * 512 + col - 512] = s;
    }
}

// =====================================================================
// Per-step small GEMM on TENSOR CORES, 256-thread variant:
// all 8 warps load (2x parallelism), warps 0-3 compute (R12 phase-A body).
// grid (40 cb, 4 ks). Partials layout identical to R11.
// =====================================================================
#define SSTR 136
#define S_AH 0
#define S_AL 17408
#define S_BH 34816
#define S_BL 52224
#define SMALL_SMEM 69632

__global__ void __launch_bounds__(256) small_mma(
    float* __restrict__ P1o, float* __restrict__ P3o)
{
    extern __shared__ char smem[];
    const uint32_t sb = smem_u32(smem);
    const int tid = threadIdx.x, lane = tid & 31, wid = tid >> 5;
    const int cb = blockIdx.x, ks = blockIdx.y;
    const int k0 = ks * 128;

    float* __restrict__ P;
    int Ncols, cbl;
    if (cb < 8) { P = P1o; Ncols = 512;  cbl = cb; }
    else        { P = P3o; Ncols = 2048; cbl = cb - 8; }

    // ---- load A (64x128) and B (64x128) hi/lo with all 256 threads ----
#pragma unroll
    for (int it = 0; it < 4; it++) {           // 1024 uint4 per array
        int idx = it * 256 + tid;
        int row = idx >> 4, c8 = (idx & 15) * 8;
        uint32_t off = (row * SSTR + c8) * 2;
        *(uint4*)(smem + S_AH + off) = *(const uint4*)&d_hbf_h[row * 512 + k0 + c8];
        *(uint4*)(smem + S_AL + off) = *(const uint4*)&d_hbf_l[row * 512 + k0 + c8];
        *(uint4*)(smem + S_BH + off) = *(const uint4*)&d_sW_h[(size_t)(cb * 64 + row) * 512 + k0 + c8];
        *(uint4*)(smem + S_BL + off) = *(const uint4*)&d_sW_l[(size_t)(cb * 64 + row) * 512 + k0 + c8];
    }
    __syncthreads();

    if (wid < 4) {
        const int wm = wid >> 1, wn = wid & 1;
        float acc[2][4][4];
#pragma unroll
        for (int i = 0; i < 2; i++)
#pragma unroll
            for (int j = 0; j < 4; j++)
#pragma unroll
                for (int q = 0; q < 4; q++) acc[i][j][q] = 0.f;

        const uint32_t a_row = wm * 32 + (lane & 15);
        const uint32_t a_k   = ((lane >> 4) & 1) * 8;
        const uint32_t b_row = wn * 32 + (lane & 7) + ((lane >> 4) & 1) * 8;
        const uint32_t b_k   = ((lane >> 3) & 1) * 8;

#pragma unroll
        for (int k16i = 0; k16i < 8; k16i++) {
            const uint32_t k16 = k16i * 16;
            uint32_t ahf[2][4], alf[2][4], bhf[2][4], blf[2][4];
#pragma unroll
            for (int mt = 0; mt < 2; mt++) {
                uint32_t off = ((a_row + mt * 16) * SSTR + k16 + a_k) * 2;
                ldsm_x4(ahf[mt], sb + S_AH + off);
                ldsm_x4(alf[mt], sb + S_AL + off);
            }
#pragma unroll
            for (int np = 0; np < 2; np++) {
                uint32_t off = ((b_row + np * 16) * SSTR + k16 + b_k) * 2;
                ldsm_x4(bhf[np], sb + S_BH + off);
                ldsm_x4(blf[np], sb + S_BL + off);
            }
#pragma unroll
            for (int mt = 0; mt < 2; mt++)
#pragma unroll
                for (int np = 0; np < 2; np++) {
                    mma_bf16(acc[mt][np * 2 + 0], ahf[mt], &bhf[np][0]);
                    mma_bf16(acc[mt][np * 2 + 1], ahf[mt], &bhf[np][2]);
                    mma_bf16(acc[mt][np * 2 + 0], ahf[mt], &blf[np][0]);
                    mma_bf16(acc[mt][np * 2 + 1], ahf[mt], &blf[np][2]);
                    mma_bf16(acc[mt][np * 2 + 0], alf[mt], &bhf[np][0]);
                    mma_bf16(acc[mt][np * 2 + 1], alf[mt], &bhf[np][2]);
                }
        }

        const int g = lane >> 2, tg = lane & 3;
#pragma unroll
        for (int mt = 0; mt < 2; mt++)
#pragma unroll
            for (int nt = 0; nt < 4; nt++) {
                int r0 = wm * 32 + mt * 16 + g;
                int c0 = cbl * 64 + wn * 32 + nt * 8 + tg * 2;
#pragma unroll
                for (int q = 0; q < 4; q++) {
                    int m = r0 + (q >> 1) * 8;
                    int n = c0 + (q & 1);
                    P[(size_t)(ks * 64 + m) * Ncols + n] = acc[mt][nt][q];
                }
            }
    }
}

// =====================================================================
// Attention scores + softmax. attn_img loaded via uint4 (8 halves/load);
// lane's 16 ah/wf values cached in registers, reused across its 4 pixels.
// grid 64, 512 threads.
// =====================================================================
__global__ void __launch_bounds__(512) attn_softmax(
    const float* __restrict__ P1,
    const float* __restrict__ tb,
    const float* __restrict__ wfull)
{
    const int n = blockIdx.x, tid = threadIdx.x;
    __shared__ float ah[512], wf[512], sc[64];
    float v = tb[tid];
#pragma unroll
    for (int s = 0; s < 4; s++) v += P1[(size_t)(s * 64 + n) * 512 + tid];
    ah[tid] = v;
    wf[tid] = wfull[tid];
    __syncthreads();

    const int warp = tid >> 5, lane = tid & 31;
    // register-cache this lane's 16 ah/wf values (chunks lane and lane+32)
    float ar[16], wr[16];
#pragma unroll
    for (int i = 0; i < 2; i++) {
        int base = (lane + 32 * i) * 8;
#pragma unroll
        for (int j = 0; j < 8; j++) {
            ar[i * 8 + j] = ah[base + j];
            wr[i * 8 + j] = wf[base + j];
        }
    }

    for (int p = warp; p < 64; p += 16) {
        const uint4* img4 = (const uint4*)&d_attn_img[(size_t)(n * 64 + p) * 512];
        float s = 0.f;
#pragma unroll
        for (int i = 0; i < 2; i++) {
            uint4 u = img4[lane + 32 * i];
            __half2 hh0 = *(__half2*)&u.x, hh1 = *(__half2*)&u.y;
            __half2 hh2 = *(__half2*)&u.z, hh3 = *(__half2*)&u.w;
            float2 f0 = __half22float2(hh0), f1 = __half22float2(hh1);
            float2 f2 = __half22float2(hh2), f3 = __half22float2(hh3);
            float im[8] = {f0.x, f0.y, f1.x, f1.y, f2.x, f2.y, f3.x, f3.y};
#pragma unroll
            for (int j = 0; j < 8; j++) {
                float e = ar[i * 8 + j] + im[j];
                if (e > 0.f) s += e * wr[i * 8 + j];
            }
        }
#pragma unroll
        for (int o = 16; o > 0; o >>= 1) s += __shfl_xor_sync(0xFFFFFFFFu, s, o);
        if (lane == 0) sc[p] = s;
    }
    __syncthreads();
    if (tid < 32) {
        float s0 = sc[tid], s1 = sc[tid + 32];
        float mx = fmaxf(s0, s1);
#pragma unroll
        for (int o = 16; o > 0; o >>= 1) mx = fmaxf(mx, __shfl_xor_sync(0xFFFFFFFFu, mx, o));
        float e0 = expf(s0 - mx), e1 = expf(s1 - mx);
        float sum = e0 + e1;
#pragma unroll
        for (int o = 16; o > 0; o >>= 1) sum += __shfl_xor_sync(0xFFFFFFFFu, sum, o);
        float inv = 1.f / sum;
        d_logits[n * 64 + tid]      = e0 * inv;
        d_logits[n * 64 + tid + 32] = e1 * inv;
    }
}

// =====================================================================
// Gates assembly + LSTM pointwise (G fp16); h out t-major for FC.
// grid (64 n, 8 hchunk), 256 threads.
// =====================================================================
__global__ void gates_lstm(const float* __restrict__ P3,
                           const float* __restrict__ pre_t,
                           const float* __restrict__ b_ih,
                           const float* __restrict__ b_hh,
                           int t)
{
    const int n = blockIdx.x, hc = blockIdx.y, tid = threadIdx.x;
    __shared__ float lg[64];
    __shared__ float sg[4][64];
    if (tid < 64) lg[tid] = d_logits[n * 64 + tid];
    __syncthreads();

    const int q = tid >> 6, hl = tid & 63;
    const int j = q * 512 + hc * 64 + hl;
    float acc = b_ih[j] + b_hh[j] + pre_t[n * 2048 + j];
#pragma unroll
    for (int s = 0; s < 4; s++) acc += P3[(size_t)(s * 64 + n) * 2048 + j];
    const uint4* g4 = (const uint4*)&d_G[((size_t)n * 2048 + j) * 64];
#pragma unroll
    for (int pi = 0; pi < 8; pi++) {
        uint4 u = g4[pi];
        __half2 h0 = *(__half2*)&u.x, h1 = *(__half2*)&u.y;
        __half2 h2 = *(__half2*)&u.z, h3 = *(__half2*)&u.w;
        float2 f0 = __half22float2(h0), f1 = __half22float2(h1);
        float2 f2 = __half22float2(h2), f3 = __half22float2(h3);
        const float* w = &lg[pi * 8];
        acc += w[0] * f0.x + w[1] * f0.y + w[2] * f1.x + w[3] * f1.y
             + w[4] * f2.x + w[5] * f2.y + w[6] * f3.x + w[7] * f3.y;
    }
    sg[q][hl] = acc;
    __syncthreads();

    if (tid < 64) {
        int hidx = hc * 64 + tid;
        float ig = sg[0][tid], fg = sg[1][tid], gg = sg[2][tid], og = sg[3][tid];
        float si = 1.f / (1.f + expf(-ig));
        float sf = 1.f / (1.f + expf(-fg));
        float so = 1.f / (1.f + expf(-og));
        float cn = sf * d_c[n * 512 + hidx] + si * tanhf(gg);
        float hn = so * tanhf(cn);
        d_c[n * 512 + hidx] = cn;
        __nv_bfloat16 hi = __float2bfloat16(hn);
        __nv_bfloat16 lo = __float2bfloat16(hn - __bfloat162float(hi));
        d_hbf_h[n * 512 + hidx] = hi;
        d_hbf_l[n * 512 + hidx] = lo;
        size_t o = ((size_t)t * NBATCH + n) * 512 + hidx;   // t-major
        d_houtbf_h[o] = hi;
        d_houtbf_l[o] = lo;
    }
}

// =====================================================================
// Host side
// =====================================================================
template <typename Tp>
static void* symaddr(Tp& ref)
{
    void* p = nullptr;
    cudaGetSymbolAddress(&p, ref);
    return p;
}

extern "C" void kernel_launch(void* const* d_in, const int* in_sizes, int n_in,
                              void* d_out, int out_size)
{
    const float* features     = (const float*)d_in[0];
    const int*   captions     = (const int*)  d_in[1];
    const float* embd_W       = (const float*)d_in[2];
    const float* attn_token_W = (const float*)d_in[3];
    const float* attn_token_b = (const float*)d_in[4];
    const float* attn_feat_W  = (const float*)d_in[5];
    const float* attn_feat_b  = (const float*)d_in[6];
    const float* attn_full_W  = (const float*)d_in[7];
    // d_in[8] attn_full_b: softmax-invariant constant -> skipped
    const float* W_ih         = (const float*)d_in[9];
    const float* b_ih         = (const float*)d_in[10];
    const float* W_hh         = (const float*)d_in[11];
    const float* b_hh         = (const float*)d_in[12];
    const float* fc_W         = (const float*)d_in[13];
    const float* fc_b         = (const float*)d_in[14];
    const float* init_Wh      = (const float*)d_in[15];
    const float* init_Wc      = (const float*)d_in[16];
    float* out = (float*)d_out;

    __nv_bfloat16* p_feat_h = (__nv_bfloat16*)symaddr(d_feat_h);
    __nv_bfloat16* p_feat_l = (__nv_bfloat16*)symaddr(d_feat_l);
    __nv_bfloat16* p_Wih_h  = (__nv_bfloat16*)symaddr(d_Wih_h);
    __nv_bfloat16* p_Wih_l  = (__nv_bfloat16*)symaddr(d_Wih_l);
    __nv_bfloat16* p_afW_h  = (__nv_bfloat16*)symaddr(d_afW_h);
    __nv_bfloat16* p_afW_l  = (__nv_bfloat16*)symaddr(d_afW_l);
    __nv_bfloat16* p_fcW_h  = (__nv_bfloat16*)symaddr(d_fcW_h);
    __nv_bfloat16* p_fcW_l  = (__nv_bfloat16*)symaddr(d_fcW_l);
    __nv_bfloat16* p_emb_h  = (__nv_bfloat16*)symaddr(d_embbf_h);
    __nv_bfloat16* p_emb_l  = (__nv_bfloat16*)symaddr(d_embbf_l);
    __nv_bfloat16* p_hbf_h  = (__nv_bfloat16*)symaddr(d_houtbf_h);
    __nv_bfloat16* p_hbf_l  = (__nv_bfloat16*)symaddr(d_houtbf_l);

    float* p_pre  = (float*)symaddr(d_pre);
    float* p_part = (float*)symaddr(d_part);
    float* p_c    = (float*)symaddr(d_c);
    float* p_P1   = (float*)symaddr(d_P1);
    float* p_P3   = (float*)symaddr(d_P3);

    // opt-in to >48KB dynamic smem (idempotent)
    cudaFuncAttributes fa;
    cudaFuncGetAttributes(&fa, mma_nt);
    if (fa.maxDynamicSharedSizeBytes < MMA_SMEM_BYTES)
        cudaFuncSetAttribute(mma_nt, cudaFuncAttributeMaxDynamicSharedMemorySize,
                             MMA_SMEM_BYTES);
    cudaFuncGetAttributes(&fa, init_mma);
    if (fa.maxDynamicSharedSizeBytes < INIT_SMEM_BYTES)
        cudaFuncSetAttribute(init_mma, cudaFuncAttributeMaxDynamicSharedMemorySize,
                             INIT_SMEM_BYTES);
    cudaFuncGetAttributes(&fa, small_mma);
    if (fa.maxDynamicSharedSizeBytes < SMALL_SMEM)
        cudaFuncSetAttribute(small_mma, cudaFuncAttributeMaxDynamicSharedMemorySize,
                             SMALL_SMEM);

    // side stream + events (host-side objects only)
    static cudaStream_t s2 = nullptr;
    static cudaEvent_t evA = nullptr, evB = nullptr;
    if (!s2) {
        cudaStreamCreateWithFlags(&s2, cudaStreamNonBlocking);
        cudaEventCreateWithFlags(&evA, cudaEventDisableTiming);
        cudaEventCreateWithFlags(&evB, cudaEventDisableTiming);
    }

    // ---- conversions (stream 0) ----
    cvt_all<<<17312, 256>>>(features, W_ih, attn_feat_W, fc_W,
                            attn_token_W, W_hh);
    cudaEventRecord(evA, 0);

    // ---- fork: init GEMM chain on s2 ----
    cudaStreamWaitEvent(s2, evA, 0);
    init_mma<<<dim3(8, NSPLIT), 256, INIT_SMEM_BYTES, s2>>>(init_Wh, init_Wc, p_part);
    reduce_init<<<256, 256, 0, s2>>>(p_part, p_c);
    cudaEventRecord(evB, s2);

    // ---- stream 0: remaining prologue ----
    emb_gather_bf<<<TSTEPS * NBATCH, 128>>>(captions, embd_W, p_emb_h, p_emb_l);
    // pre_emb = emb @ W_ih[:,1536:]^T  (2048 x 2048, K=512)
    mma_nt<<<dim3(32, 16, 1), 256, MMA_SMEM_BYTES>>>(
        p_emb_h, p_emb_l, EMBD, TSTEPS * NBATCH, p_Wih_h + 1536, p_Wih_l + 1536, G4,
        p_pre, G4, G4, 8, nullptr, 0, 0);
    // merged: attn_img (fp16) + G (fp16)
    mma_nt<<<dim3(40, 32, 1), 256, MMA_SMEM_BYTES>>>(
        p_feat_h, p_feat_l, ENCC, MROWS, p_afW_h, p_afW_l, ENCC,
        nullptr, ADIM, ADIM, 24, attn_feat_b, 3, 0);

    // ---- join: h0/c0 ready before the recurrence ----
    cudaStreamWaitEvent((cudaStream_t)0, evB, 0);

    // ---- sequential recurrence: 3 launches per step (proven-final shape) ----
    for (int t = 0; t < TSTEPS; ++t) {
        small_mma<<<dim3(40, 4), 256, SMALL_SMEM>>>(p_P1, p_P3);
        attn_softmax<<<64, 512>>>(p_P1, attn_token_b, attn_full_W);
        gates_lstm<<<dim3(64, 8), 256>>>(p_P3, p_pre + (size_t)t * NBATCH * G4,
                                         b_ih, b_hh, t);
    }

    // ---- epilogue: FC over all timesteps (t-major rows, mode 5) ----
    mma_nt<<<dim3(157, 16, 1), 256, MMA_SMEM_BYTES>>>(
        p_hbf_h, p_hbf_l, HDIM, TSTEPS * NBATCH, p_fcW_h, p_fcW_l, HDIM,
        out, VOCAB, VOCAB, 8, fc_b, 5, 0);
}

// round 17
// speedup vs baseline: 1.1577x; 1.0056x over previous
#include <cuda_runtime.h>
#include <cuda_bf16.h>
#include <cuda_fp16.h>
#include <cstdint>
#include <math.h>

// ---------------- problem constants ----------------
#define TSTEPS 32
#define NBATCH 64
#define NPIX   64
#define ENCC   1536
#define EMBD   512
#define ADIM   512
#define HDIM   512
#define G4     2048     // 4*H
#define VOCAB  10000
#define VPAD   10048    // 157*64
#define MROWS  4096     // N*P
#define KINIT  98304    // P*ENC
#define NSPLIT 96       // init split-K

// ---------------- scratch (__device__ globals; no allocation) ----------------
__device__ __align__(16) __nv_bfloat16 d_feat_h[MROWS * ENCC];
__device__ __align__(16) __nv_bfloat16 d_feat_l[MROWS * ENCC];
__device__ __align__(16) __nv_bfloat16 d_Wih_h[G4 * G4];
__device__ __align__(16) __nv_bfloat16 d_Wih_l[G4 * G4];
__device__ __align__(16) __nv_bfloat16 d_afW_h[ADIM * ENCC];
__device__ __align__(16) __nv_bfloat16 d_afW_l[ADIM * ENCC];
__device__ __align__(16) __nv_bfloat16 d_fcW_h[VPAD * HDIM];
__device__ __align__(16) __nv_bfloat16 d_fcW_l[VPAD * HDIM];
__device__ __align__(16) __nv_bfloat16 d_embbf_h[TSTEPS * NBATCH * EMBD];
__device__ __align__(16) __nv_bfloat16 d_embbf_l[TSTEPS * NBATCH * EMBD];
// t-major hidden outputs: [t*64+n][512]
__device__ __align__(16) __nv_bfloat16 d_houtbf_h[TSTEPS * NBATCH * HDIM];
__device__ __align__(16) __nv_bfloat16 d_houtbf_l[TSTEPS * NBATCH * HDIM];
// stacked small-GEMM weights: rows 0-511 attn_token_W, rows 512-2559 W_hh
__device__ __align__(16) __nv_bfloat16 d_sW_h[2560 * 512];
__device__ __align__(16) __nv_bfloat16 d_sW_l[2560 * 512];
// per-step h in bf16 hi/lo
__device__ __align__(16) __nv_bfloat16 d_hbf_h[NBATCH * HDIM];
__device__ __align__(16) __nv_bfloat16 d_hbf_l[NBATCH * HDIM];

__device__ __align__(16) __half d_attn_img[MROWS * ADIM];            // fp16, 4 MB
__device__ __align__(16) __half d_G[(size_t)NBATCH * G4 * NPIX];     // fp16, 16.7 MB
__device__ float d_pre[TSTEPS * NBATCH * G4];
__device__ float d_part[NSPLIT * 64 * 1024];       // init split-K partials (25MB)
__device__ float d_c[NBATCH * HDIM];
__device__ float d_P1[4 * NBATCH * ADIM];
__device__ float d_P3[4 * NBATCH * G4];
__device__ float d_logits[NBATCH * NPIX];

// =====================================================================
// warp-MMA + cp.async helpers (sm_80+ PTX, no arch-feature gating)
// =====================================================================
__device__ __forceinline__ uint32_t smem_u32(const void* p) {
    uint32_t a;
    asm("{ .reg .u64 t; cvta.to.shared.u64 t, %1; cvt.u32.u64 %0, t; }" : "=r"(a) : "l"(p));
    return a;
}
__device__ __forceinline__ void ldsm_x4(uint32_t* r, uint32_t addr) {
    asm volatile("ldmatrix.sync.aligned.m8n8.x4.shared.b16 {%0,%1,%2,%3}, [%4];"
                 : "=r"(r[0]), "=r"(r[1]), "=r"(r[2]), "=r"(r[3]) : "r"(addr));
}
__device__ __forceinline__ void ldsm_x4_t(uint32_t* r, uint32_t addr) {
    asm volatile("ldmatrix.sync.aligned.m8n8.x4.trans.shared.b16 {%0,%1,%2,%3}, [%4];"
                 : "=r"(r[0]), "=r"(r[1]), "=r"(r[2]), "=r"(r[3]) : "r"(addr));
}
__device__ __forceinline__ void mma_bf16(float* c, const uint32_t* a, const uint32_t* b) {
    asm volatile(
        "mma.sync.aligned.m16n8k16.row.col.f32.bf16.bf16.f32 "
        "{%0,%1,%2,%3}, {%4,%5,%6,%7}, {%8,%9}, {%0,%1,%2,%3};"
        : "+f"(c[0]), "+f"(c[1]), "+f"(c[2]), "+f"(c[3])
        : "r"(a[0]), "r"(a[1]), "r"(a[2]), "r"(a[3]), "r"(b[0]), "r"(b[1]));
}
__device__ __forceinline__ void cp16(uint32_t dst, const void* src, bool pred) {
    int sz = pred ? 16 : 0;
    asm volatile("cp.async.cg.shared.global [%0], [%1], 16, %2;"
                 :: "r"(dst), "l"(src), "r"(sz) : "memory");
}
#define CP_COMMIT() asm volatile("cp.async.commit_group;" ::: "memory")
#define CP_WAIT1()  asm volatile("cp.async.wait_group 1;" ::: "memory")

// =====================================================================
// fp32 -> bf16 hi/lo conversion, main segments (stream0 critical path):
// feat 6144 | Wih 4096 | afW 768   (11008 blocks)
// =====================================================================
__global__ void cvt_main(const float* __restrict__ feat,
                         const float* __restrict__ Wih,
                         const float* __restrict__ afW)
{
    int b = blockIdx.x;
    const float* src;
    __nv_bfloat16 *dh, *dl;
    int n_src, lb;
    if (b < 6144)       { src = feat; dh = d_feat_h; dl = d_feat_l; n_src = MROWS * ENCC; lb = b; }
    else if (b < 10240) { src = Wih;  dh = d_Wih_h;  dl = d_Wih_l;  n_src = G4 * G4;      lb = b - 6144; }
    else                { src = afW;  dh = d_afW_h;  dl = d_afW_l;  n_src = ADIM * ENCC;  lb = b - 10240; }
    int i = (lb * 256 + threadIdx.x) * 4;
    float4 v = make_float4(0.f, 0.f, 0.f, 0.f);
    if (i < n_src) v = *(const float4*)&src[i];
    float a[4] = {v.x, v.y, v.z, v.w};
    __nv_bfloat16 h[4], l[4];
#pragma unroll
    for (int j = 0; j < 4; j++) {
        h[j] = __float2bfloat16(a[j]);
        l[j] = __float2bfloat16(a[j] - __bfloat162float(h[j]));
    }
    *(__nv_bfloat162*)&dh[i]     = __halves2bfloat162(h[0], h[1]);
    *(__nv_bfloat162*)&dh[i + 2] = __halves2bfloat162(h[2], h[3]);
    *(__nv_bfloat162*)&dl[i]     = __halves2bfloat162(l[0], l[1]);
    *(__nv_bfloat162*)&dl[i + 2] = __halves2bfloat162(l[2], l[3]);
}

// aux segments (s2, hidden behind stream0): fcW 5024 | tokW 256 | Whh 1024
__global__ void cvt_aux(const float* __restrict__ fcW,
                        const float* __restrict__ tokW,
                        const float* __restrict__ Whh)
{
    int b = blockIdx.x;
    const float* src;
    __nv_bfloat16 *dh, *dl;
    int n_src, lb;
    if (b < 5024)      { src = fcW;  dh = d_fcW_h; dl = d_fcW_l; n_src = VOCAB * HDIM; lb = b; }
    else if (b < 5280) { src = tokW; dh = d_sW_h;  dl = d_sW_l;  n_src = 512 * 512;    lb = b - 5024; }
    else               { src = Whh;  dh = d_sW_h + 262144; dl = d_sW_l + 262144;
                         n_src = 2048 * 512; lb = b - 5280; }
    int i = (lb * 256 + threadIdx.x) * 4;
    float4 v = make_float4(0.f, 0.f, 0.f, 0.f);
    if (i < n_src) v = *(const float4*)&src[i];
    float a[4] = {v.x, v.y, v.z, v.w};
    __nv_bfloat16 h[4], l[4];
#pragma unroll
    for (int j = 0; j < 4; j++) {
        h[j] = __float2bfloat16(a[j]);
        l[j] = __float2bfloat16(a[j] - __bfloat162float(h[j]));
    }
    *(__nv_bfloat162*)&dh[i]     = __halves2bfloat162(h[0], h[1]);
    *(__nv_bfloat162*)&dh[i + 2] = __halves2bfloat162(h[2], h[3]);
    *(__nv_bfloat162*)&dl[i]     = __halves2bfloat162(l[0], l[1]);
    *(__nv_bfloat162*)&dl[i + 2] = __halves2bfloat162(l[2], l[3]);
}

// embedding gather straight into bf16 hi/lo [t*64+n][e]
__global__ void emb_gather_bf(const int* __restrict__ cap,
                              const float* __restrict__ EW,
                              __nv_bfloat16* __restrict__ dh,
                              __nv_bfloat16* __restrict__ dl)
{
    int m = blockIdx.x;                 // t*64+n
    int n = m & 63, t = m >> 6;
    int tok = cap[n * TSTEPS + t];
    int i = threadIdx.x * 4;            // 128 thr * 4 = 512
    float4 v = *(const float4*)&EW[(size_t)tok * EMBD + i];
    float a[4] = {v.x, v.y, v.z, v.w};
    __nv_bfloat16 h[4], l[4];
#pragma unroll
    for (int j = 0; j < 4; j++) {
        h[j] = __float2bfloat16(a[j]);
        l[j] = __float2bfloat16(a[j] - __bfloat162float(h[j]));
    }
    size_t o = (size_t)m * EMBD + i;
    *(__nv_bfloat162*)&dh[o]     = __halves2bfloat162(h[0], h[1]);
    *(__nv_bfloat162*)&dh[o + 2] = __halves2bfloat162(h[2], h[3]);
    *(__nv_bfloat162*)&dl[o]     = __halves2bfloat162(l[0], l[1]);
    *(__nv_bfloat162*)&dl[o + 2] = __halves2bfloat162(l[2], l[3]);
}

// =====================================================================
// Warp-MMA NT GEMM, bf16 hi/lo split, fp32 accumulate, cp.async 2-stage.
// mode 0: fp32 C[m*ldc+n] (+bias)
// mode 3: merged — blockIdx.x<8: attn_img fp16 (+bias); else G fp16 layout
// mode 5: FC — A rows t-major (global row = moff+m), store [n][t][v] +bias
// =====================================================================
#define ASTR 72
#define AH_OFF 0
#define AL_OFF 18432
#define BH_OFF 36864
#define BL_OFF 46080
#define STAGE_BYTES 55296
#define MMA_SMEM_BYTES (2 * STAGE_BYTES)

__global__ void __launch_bounds__(256) mma_nt(
    const __nv_bfloat16* __restrict__ Ah, const __nv_bfloat16* __restrict__ Al,
    int lda, int Mvalid,
    const __nv_bfloat16* __restrict__ Bh, const __nv_bfloat16* __restrict__ Bl,
    int ldb,
    float* __restrict__ C, int Nvalid, int ldc,
    int chunks, const float* __restrict__ bias, int mode, int moff)
{
    extern __shared__ char smem[];
    const uint32_t sb = smem_u32(smem);
    const int tid = threadIdx.x, lane = tid & 31, wid = tid >> 5;
    const int wm = wid >> 1, wn = wid & 1;
    const int m0 = blockIdx.y * 128;

    const __nv_bfloat16* bH = Bh;
    const __nv_bfloat16* bL = Bl;
    const float* bptr = bias;
    int n0 = blockIdx.x * 64;
    int mode_eff = mode;
    if (mode == 3) {
        if (blockIdx.x < 8) {
            mode_eff = 4;
        } else {
            bH = d_Wih_h; bL = d_Wih_l; ldb = G4;
            bptr = nullptr;
            n0 = (blockIdx.x - 8) * 64;
            mode_eff = 1;
        }
    }

    float acc[2][4][4];
#pragma unroll
    for (int i = 0; i < 2; i++)
#pragma unroll
        for (int j = 0; j < 4; j++)
#pragma unroll
            for (int q = 0; q < 4; q++) acc[i][j][q] = 0.f;

    const uint32_t a_row = wm * 32 + (lane & 15);
    const uint32_t a_k   = ((lane >> 4) & 1) * 8;
    const uint32_t b_row = wn * 32 + (lane & 7) + ((lane >> 4) & 1) * 8;
    const uint32_t b_k   = ((lane >> 3) & 1) * 8;

    auto load_stage = [&](int ic, int st) {
        const uint32_t stb = sb + st * STAGE_BYTES;
        const long long kc = (long long)ic * 64;
#pragma unroll
        for (int it = 0; it < 4; it++) {
            int idx = it * 256 + tid;
            int row = idx >> 3, k8 = (idx & 7) * 8;
            int m = m0 + row;
            bool p = (m < Mvalid);
            int mc = p ? m : (Mvalid - 1);
            uint32_t off = (row * ASTR + k8) * 2;
            cp16(stb + AH_OFF + off, &Ah[(size_t)mc * lda + kc + k8], p);
            cp16(stb + AL_OFF + off, &Al[(size_t)mc * lda + kc + k8], p);
        }
#pragma unroll
        for (int it = 0; it < 2; it++) {
            int idx = it * 256 + tid;
            int row = idx >> 3, k8 = (idx & 7) * 8;
            uint32_t off = (row * ASTR + k8) * 2;
            cp16(stb + BH_OFF + off, &bH[(size_t)(n0 + row) * ldb + kc + k8], true);
            cp16(stb + BL_OFF + off, &bL[(size_t)(n0 + row) * ldb + kc + k8], true);
        }
    };

    load_stage(0, 0);
    CP_COMMIT();

    for (int ic = 0; ic < chunks; ic++) {
        const int s = ic & 1;
        if (ic + 1 < chunks) load_stage(ic + 1, s ^ 1);
        CP_COMMIT();
        CP_WAIT1();
        __syncthreads();

        const uint32_t stb = sb + s * STAGE_BYTES;
#pragma unroll
        for (int ks = 0; ks < 4; ks++) {
            const uint32_t k16 = ks * 16;
            uint32_t ahf[2][4], alf[2][4], bhf[2][4], blf[2][4];
#pragma unroll
            for (int mt = 0; mt < 2; mt++) {
                uint32_t off = ((a_row + mt * 16) * ASTR + k16 + a_k) * 2;
                ldsm_x4(ahf[mt], stb + AH_OFF + off);
                ldsm_x4(alf[mt], stb + AL_OFF + off);
            }
#pragma unroll
            for (int np = 0; np < 2; np++) {
                uint32_t off = ((b_row + np * 16) * ASTR + k16 + b_k) * 2;
                ldsm_x4(bhf[np], stb + BH_OFF + off);
                ldsm_x4(blf[np], stb + BL_OFF + off);
            }
#pragma unroll
            for (int mt = 0; mt < 2; mt++)
#pragma unroll
                for (int np = 0; np < 2; np++) {
                    mma_bf16(acc[mt][np * 2 + 0], ahf[mt], &bhf[np][0]);
                    mma_bf16(acc[mt][np * 2 + 1], ahf[mt], &bhf[np][2]);
                    mma_bf16(acc[mt][np * 2 + 0], ahf[mt], &blf[np][0]);
                    mma_bf16(acc[mt][np * 2 + 1], ahf[mt], &blf[np][2]);
                    mma_bf16(acc[mt][np * 2 + 0], alf[mt], &bhf[np][0]);
                    mma_bf16(acc[mt][np * 2 + 1], alf[mt], &bhf[np][2]);
                }
        }
        __syncthreads();
    }

    const int g = lane >> 2, tg = lane & 3;
#pragma unroll
    for (int mt = 0; mt < 2; mt++) {
#pragma unroll
        for (int nt = 0; nt < 4; nt++) {
            int r0 = m0 + wm * 32 + mt * 16 + g;
            int c0 = n0 + wn * 32 + nt * 8 + tg * 2;
#pragma unroll
            for (int q = 0; q < 4; q++) {
                int m = r0 + (q >> 1) * 8;
                int n = c0 + (q & 1);
                if (m >= Mvalid) continue;
                float v = acc[mt][nt][q];
                if (mode_eff == 1) {
                    int nb = m >> 6, p = m & 63;
                    d_G[((size_t)nb * 2048 + n) * 64 + p] = __float2half(v);
                } else if (mode_eff == 4) {
                    d_attn_img[(size_t)m * ADIM + n] = __float2half(v + bptr[n]);
                } else if (mode_eff == 5) {
                    if (n < Nvalid) {
                        int gm = moff + m;          // global row, t-major
                        int tt = gm >> 6, nb = gm & 63;
                        C[(size_t)(nb * TSTEPS + tt) * ldc + n] = v + bptr[n];
                    }
                } else {
                    if (n < Nvalid) {
                        if (bptr) v += bptr[n];
                        C[(size_t)m * ldc + n] = v;
                    }
                }
            }
        }
    }
}

// =====================================================================
// Fused init GEMM: h0|c0 = F(64x98304) @ [Wh|Wc]; split-K 96.
// =====================================================================
#define IBSTR 136
#define IA_H 0
#define IA_L 9216
#define IB_H 18432
#define IB_L 35840
#define INIT_SMEM_BYTES 53248

__global__ void __launch_bounds__(256) init_mma(
    const float* __restrict__ Wh, const float* __restrict__ Wc,
    float* __restrict__ P)
{
    extern __shared__ char smem[];
    const uint32_t sb = smem_u32(smem);
    __nv_bfloat16* Bsh = (__nv_bfloat16*)(smem + IB_H);
    __nv_bfloat16* Bsl = (__nv_bfloat16*)(smem + IB_L);
    const int tid = threadIdx.x, lane = tid & 31, wid = tid >> 5;
    const int wm = wid >> 2, wn = wid & 3;
    const int bx = blockIdx.x;
    const float* __restrict__ W = (bx < 4) ? Wh : Wc;
    const int n0g = (bx & 3) * 128;
    const int outc0 = bx * 128;
    const size_t k0 = (size_t)blockIdx.y * 1024;

    float acc[2][4][4];
#pragma unroll
    for (int i = 0; i < 2; i++)
#pragma unroll
        for (int j = 0; j < 4; j++)
#pragma unroll
            for (int q = 0; q < 4; q++) acc[i][j][q] = 0.f;

    const uint32_t a_row = wm * 32 + (lane & 15);
    const uint32_t a_k   = ((lane >> 4) & 1) * 8;
    const uint32_t bt_k = ((lane >> 3) & 1) * 8 + (lane & 7);
    const uint32_t bt_n = ((lane >> 4) & 1) * 8;

    for (int ic = 0; ic < 16; ic++) {
        const size_t kg = k0 + ic * 64;
#pragma unroll
        for (int it = 0; it < 2; it++) {
            int idx = it * 256 + tid;
            int row = idx >> 3, k8 = (idx & 7) * 8;
            uint32_t off = (row * ASTR + k8) * 2;
            *(uint4*)(smem + IA_H + off) = *(const uint4*)&d_feat_h[(size_t)row * KINIT + kg + k8];
            *(uint4*)(smem + IA_L + off) = *(const uint4*)&d_feat_l[(size_t)row * KINIT + kg + k8];
        }
#pragma unroll
        for (int it = 0; it < 8; it++) {
            int idx = it * 256 + tid;
            int kk = idx >> 5, nn = (idx & 31) * 4;
            float4 v = *(const float4*)&W[(kg + kk) * 512 + n0g + nn];
            float a[4] = {v.x, v.y, v.z, v.w};
            __nv_bfloat16 h[4], l[4];
#pragma unroll
            for (int j = 0; j < 4; j++) {
                h[j] = __float2bfloat16(a[j]);
                l[j] = __float2bfloat16(a[j] - __bfloat162float(h[j]));
            }
            int o = kk * IBSTR + nn;
            *(__nv_bfloat162*)&Bsh[o]     = __halves2bfloat162(h[0], h[1]);
            *(__nv_bfloat162*)&Bsh[o + 2] = __halves2bfloat162(h[2], h[3]);
            *(__nv_bfloat162*)&Bsl[o]     = __halves2bfloat162(l[0], l[1]);
            *(__nv_bfloat162*)&Bsl[o + 2] = __halves2bfloat162(l[2], l[3]);
        }
        __syncthreads();

#pragma unroll
        for (int ks = 0; ks < 4; ks++) {
            const uint32_t k16 = ks * 16;
            uint32_t ahf[2][4], alf[2][4];
#pragma unroll
            for (int mt = 0; mt < 2; mt++) {
                uint32_t off = ((a_row + mt * 16) * ASTR + k16 + a_k) * 2;
                ldsm_x4(ahf[mt], sb + IA_H + off);
                ldsm_x4(alf[mt], sb + IA_L + off);
            }
#pragma unroll
            for (int ng = 0; ng < 2; ng++) {
                uint32_t bhf[4], blf[4];
                uint32_t off = ((k16 + bt_k) * IBSTR + wn * 32 + ng * 16 + bt_n) * 2;
                ldsm_x4_t(bhf, sb + IB_H + off);
                ldsm_x4_t(blf, sb + IB_L + off);
#pragma unroll
                for (int mt = 0; mt < 2; mt++) {
                    mma_bf16(acc[mt][ng * 2 + 0], ahf[mt], &bhf[0]);
                    mma_bf16(acc[mt][ng * 2 + 1], ahf[mt], &bhf[2]);
                    mma_bf16(acc[mt][ng * 2 + 0], ahf[mt], &blf[0]);
                    mma_bf16(acc[mt][ng * 2 + 1], ahf[mt], &blf[2]);
                    mma_bf16(acc[mt][ng * 2 + 0], alf[mt], &bhf[0]);
                    mma_bf16(acc[mt][ng * 2 + 1], alf[mt], &bhf[2]);
                }
            }
        }
        __syncthreads();
    }

    const int g = lane >> 2, tg = lane & 3;
    const int zb = blockIdx.y * 64;
#pragma unroll
    for (int mt = 0; mt < 2; mt++)
#pragma unroll
        for (int nt = 0; nt < 4; nt++) {
            int r0 = wm * 32 + mt * 16 + g;
            int c0 = outc0 + wn * 32 + nt * 8 + tg * 2;
#pragma unroll
            for (int q = 0; q < 4; q++) {
                int m = r0 + (q >> 1) * 8;
                int n = c0 + (q & 1);
                P[(size_t)(zb + m) * 1024 + n] = acc[mt][nt][q];
            }
        }
}

// deterministic reduce of NSPLIT split-K partials -> h0 (bf16 hi/lo), c0
__global__ void reduce_init(const float* __restrict__ P,
                            float* __restrict__ c)
{
    int r = blockIdx.x * 256 + threadIdx.x;   // 65536
    float s = 0.f;
#pragma unroll
    for (int j = 0; j < NSPLIT; j++) s += P[(size_t)j * 65536 + r];
    int m = r >> 10, col = r & 1023;
    if (col < 512) {
        __nv_bfloat16 hi = __float2bfloat16(s);
        d_hbf_h[m * 512 + col] = hi;
        d_hbf_l[m * 512 + col] = __float2bfloat16(s - __bfloat162float(hi));
    } else {
        c[m * 512 + col - 512] = s;
    }
}

// =====================================================================
// Per-step small GEMM on TENSOR CORES, 256-thread variant (R16) with
// float2-coalesced epilogue stores.
// =====================================================================
#define SSTR 136
#define S_AH 0
#define S_AL 17408
#define S_BH 34816
#define S_BL 52224
#define SMALL_SMEM 69632

__global__ void __launch_bounds__(256) small_mma(
    float* __restrict__ P1o, float* __restrict__ P3o)
{
    extern __shared__ char smem[];
    const uint32_t sb = smem_u32(smem);
    const int tid = threadIdx.x, lane = tid & 31, wid = tid >> 5;
    const int cb = blockIdx.x, ks = blockIdx.y;
    const int k0 = ks * 128;

    float* __restrict__ P;
    int Ncols, cbl;
    if (cb < 8) { P = P1o; Ncols = 512;  cbl = cb; }
    else        { P = P3o; Ncols = 2048; cbl = cb - 8; }

    // ---- load A (64x128) and B (64x128) hi/lo with all 256 threads ----
#pragma unroll
    for (int it = 0; it < 4; it++) {           // 1024 uint4 per array
        int idx = it * 256 + tid;
        int row = idx >> 4, c8 = (idx & 15) * 8;
        uint32_t off = (row * SSTR + c8) * 2;
        *(uint4*)(smem + S_AH + off) = *(const uint4*)&d_hbf_h[row * 512 + k0 + c8];
        *(uint4*)(smem + S_AL + off) = *(const uint4*)&d_hbf_l[row * 512 + k0 + c8];
        *(uint4*)(smem + S_BH + off) = *(const uint4*)&d_sW_h[(size_t)(cb * 64 + row) * 512 + k0 + c8];
        *(uint4*)(smem + S_BL + off) = *(const uint4*)&d_sW_l[(size_t)(cb * 64 + row) * 512 + k0 + c8];
    }
    __syncthreads();

    if (wid < 4) {
        const int wm = wid >> 1, wn = wid & 1;
        float acc[2][4][4];
#pragma unroll
        for (int i = 0; i < 2; i++)
#pragma unroll
            for (int j = 0; j < 4; j++)
#pragma unroll
                for (int q = 0; q < 4; q++) acc[i][j][q] = 0.f;

        const uint32_t a_row = wm * 32 + (lane & 15);
        const uint32_t a_k   = ((lane >> 4) & 1) * 8;
        const uint32_t b_row = wn * 32 + (lane & 7) + ((lane >> 4) & 1) * 8;
        const uint32_t b_k   = ((lane >> 3) & 1) * 8;

#pragma unroll
        for (int k16i = 0; k16i < 8; k16i++) {
            const uint32_t k16 = k16i * 16;
            uint32_t ahf[2][4], alf[2][4], bhf[2][4], blf[2][4];
#pragma unroll
            for (int mt = 0; mt < 2; mt++) {
                uint32_t off = ((a_row + mt * 16) * SSTR + k16 + a_k) * 2;
                ldsm_x4(ahf[mt], sb + S_AH + off);
                ldsm_x4(alf[mt], sb + S_AL + off);
            }
#pragma unroll
            for (int np = 0; np < 2; np++) {
                uint32_t off = ((b_row + np * 16) * SSTR + k16 + b_k) * 2;
                ldsm_x4(bhf[np], sb + S_BH + off);
                ldsm_x4(blf[np], sb + S_BL + off);
            }
#pragma unroll
            for (int mt = 0; mt < 2; mt++)
#pragma unroll
                for (int np = 0; np < 2; np++) {
                    mma_bf16(acc[mt][np * 2 + 0], ahf[mt], &bhf[np][0]);
                    mma_bf16(acc[mt][np * 2 + 1], ahf[mt], &bhf[np][2]);
                    mma_bf16(acc[mt][np * 2 + 0], ahf[mt], &blf[np][0]);
                    mma_bf16(acc[mt][np * 2 + 1], ahf[mt], &blf[np][2]);
                    mma_bf16(acc[mt][np * 2 + 0], alf[mt], &bhf[np][0]);
                    mma_bf16(acc[mt][np * 2 + 1], alf[mt], &bhf[np][2]);
                }
        }

        // ---- epilogue: float2-coalesced stores ----
        const int g = lane >> 2, tg = lane & 3;
#pragma unroll
        for (int mt = 0; mt < 2; mt++)
#pragma unroll
            for (int nt = 0; nt < 4; nt++) {
                int r0 = wm * 32 + mt * 16 + g;
                int c0 = cbl * 64 + wn * 32 + nt * 8 + tg * 2;
#pragma unroll
                for (int half = 0; half < 2; half++) {
                    int m = r0 + half * 8;
                    float2 v2 = make_float2(acc[mt][nt][half * 2 + 0],
                                            acc[mt][nt][half * 2 + 1]);
                    *(float2*)&P[(size_t)(ks * 64 + m) * Ncols + c0] = v2;
                }
            }
    }
}

// =====================================================================
// Attention scores + softmax (R16 uint4 + register-cached version).
// =====================================================================
__global__ void __launch_bounds__(512) attn_softmax(
    const float* __restrict__ P1,
    const float* __restrict__ tb,
    const float* __restrict__ wfull)
{
    const int n = blockIdx.x, tid = threadIdx.x;
    __shared__ float ah[512], wf[512], sc[64];
    float v = tb[tid];
#pragma unroll
    for (int s = 0; s < 4; s++) v += P1[(size_t)(s * 64 + n) * 512 + tid];
    ah[tid] = v;
    wf[tid] = wfull[tid];
    __syncthreads();

    const int warp = tid >> 5, lane = tid & 31;
    float ar[16], wr[16];
#pragma unroll
    for (int i = 0; i < 2; i++) {
        int base = (lane + 32 * i) * 8;
#pragma unroll
        for (int j = 0; j < 8; j++) {
            ar[i * 8 + j] = ah[base + j];
            wr[i * 8 + j] = wf[base + j];
        }
    }

    for (int p = warp; p < 64; p += 16) {
        const uint4* img4 = (const uint4*)&d_attn_img[(size_t)(n * 64 + p) * 512];
        float s = 0.f;
#pragma unroll
        for (int i = 0; i < 2; i++) {
            uint4 u = img4[lane + 32 * i];
            __half2 hh0 = *(__half2*)&u.x, hh1 = *(__half2*)&u.y;
            __half2 hh2 = *(__half2*)&u.z, hh3 = *(__half2*)&u.w;
            float2 f0 = __half22float2(hh0), f1 = __half22float2(hh1);
            float2 f2 = __half22float2(hh2), f3 = __half22float2(hh3);
            float im[8] = {f0.x, f0.y, f1.x, f1.y, f2.x, f2.y, f3.x, f3.y};
#pragma unroll
            for (int j = 0; j < 8; j++) {
                float e = ar[i * 8 + j] + im[j];
                if (e > 0.f) s += e * wr[i * 8 + j];
            }
        }
#pragma unroll
        for (int o = 16; o > 0; o >>= 1) s += __shfl_xor_sync(0xFFFFFFFFu, s, o);
        if (lane == 0) sc[p] = s;
    }
    __syncthreads();
    if (tid < 32) {
        float s0 = sc[tid], s1 = sc[tid + 32];
        float mx = fmaxf(s0, s1);
#pragma unroll
        for (int o = 16; o > 0; o >>= 1) mx = fmaxf(mx, __shfl_xor_sync(0xFFFFFFFFu, mx, o));
        float e0 = expf(s0 - mx), e1 = expf(s1 - mx);
        float sum = e0 + e1;
#pragma unroll
        for (int o = 16; o > 0; o >>= 1) sum += __shfl_xor_sync(0xFFFFFFFFu, sum, o);
        float inv = 1.f / sum;
        d_logits[n * 64 + tid]      = e0 * inv;
        d_logits[n * 64 + tid + 32] = e1 * inv;
    }
}

// =====================================================================
// Gates assembly + LSTM pointwise (G fp16); h out t-major for FC.
// grid (64 n, 8 hchunk), 256 threads.
// =====================================================================
__global__ void gates_lstm(const float* __restrict__ P3,
                           const float* __restrict__ pre_t,
                           const float* __restrict__ b_ih,
                           const float* __restrict__ b_hh,
                           int t)
{
    const int n = blockIdx.x, hc = blockIdx.y, tid = threadIdx.x;
    __shared__ float lg[64];
    __shared__ float sg[4][64];
    if (tid < 64) lg[tid] = d_logits[n * 64 + tid];
    __syncthreads();

    const int q = tid >> 6, hl = tid & 63;
    const int j = q * 512 + hc * 64 + hl;
    float acc = b_ih[j] + b_hh[j] + pre_t[n * 2048 + j];
#pragma unroll
    for (int s = 0; s < 4; s++) acc += P3[(size_t)(s * 64 + n) * 2048 + j];
    const uint4* g4 = (const uint4*)&d_G[((size_t)n * 2048 + j) * 64];
#pragma unroll
    for (int pi = 0; pi < 8; pi++) {
        uint4 u = g4[pi];
        __half2 h0 = *(__half2*)&u.x, h1 = *(__half2*)&u.y;
        __half2 h2 = *(__half2*)&u.z, h3 = *(__half2*)&u.w;
        float2 f0 = __half22float2(h0), f1 = __half22float2(h1);
        float2 f2 = __half22float2(h2), f3 = __half22float2(h3);
        const float* w = &lg[pi * 8];
        acc += w[0] * f0.x + w[1] * f0.y + w[2] * f1.x + w[3] * f1.y
             + w[4] * f2.x + w[5] * f2.y + w[6] * f3.x + w[7] * f3.y;
    }
    sg[q][hl] = acc;
    __syncthreads();

    if (tid < 64) {
        int hidx = hc * 64 + tid;
        float ig = sg[0][tid], fg = sg[1][tid], gg = sg[2][tid], og = sg[3][tid];
        float si = 1.f / (1.f + expf(-ig));
        float sf = 1.f / (1.f + expf(-fg));
        float so = 1.f / (1.f + expf(-og));
        float cn = sf * d_c[n * 512 + hidx] + si * tanhf(gg);
        float hn = so * tanhf(cn);
        d_c[n * 512 + hidx] = cn;
        __nv_bfloat16 hi = __float2bfloat16(hn);
        __nv_bfloat16 lo = __float2bfloat16(hn - __bfloat162float(hi));
        d_hbf_h[n * 512 + hidx] = hi;
        d_hbf_l[n * 512 + hidx] = lo;
        size_t o = ((size_t)t * NBATCH + n) * 512 + hidx;   // t-major
        d_houtbf_h[o] = hi;
        d_houtbf_l[o] = lo;
    }
}

// =====================================================================
// Host side
// =====================================================================
template <typename Tp>
static void* symaddr(Tp& ref)
{
    void* p = nullptr;
    cudaGetSymbolAddress(&p, ref);
    return p;
}

extern "C" void kernel_launch(void* const* d_in, const int* in_sizes, int n_in,
                              void* d_out, int out_size)
{
    const float* features     = (const float*)d_in[0];
    const int*   captions     = (const int*)  d_in[1];
    const float* embd_W       = (const float*)d_in[2];
    const float* attn_token_W = (const float*)d_in[3];
    const float* attn_token_b = (const float*)d_in[4];
    const float* attn_feat_W  = (const float*)d_in[5];
    const float* attn_feat_b  = (const float*)d_in[6];
    const float* attn_full_W  = (const float*)d_in[7];
    // d_in[8] attn_full_b: softmax-invariant constant -> skipped
    const float* W_ih         = (const float*)d_in[9];
    const float* b_ih         = (const float*)d_in[10];
    const float* W_hh         = (const float*)d_in[11];
    const float* b_hh         = (const float*)d_in[12];
    const float* fc_W         = (const float*)d_in[13];
    const float* fc_b         = (const float*)d_in[14];
    const float* init_Wh      = (const float*)d_in[15];
    const float* init_Wc      = (const float*)d_in[16];
    float* out = (float*)d_out;

    __nv_bfloat16* p_feat_h = (__nv_bfloat16*)symaddr(d_feat_h);
    __nv_bfloat16* p_feat_l = (__nv_bfloat16*)symaddr(d_feat_l);
    __nv_bfloat16* p_Wih_h  = (__nv_bfloat16*)symaddr(d_Wih_h);
    __nv_bfloat16* p_Wih_l  = (__nv_bfloat16*)symaddr(d_Wih_l);
    __nv_bfloat16* p_afW_h  = (__nv_bfloat16*)symaddr(d_afW_h);
    __nv_bfloat16* p_afW_l  = (__nv_bfloat16*)symaddr(d_afW_l);
    __nv_bfloat16* p_fcW_h  = (__nv_bfloat16*)symaddr(d_fcW_h);
    __nv_bfloat16* p_fcW_l  = (__nv_bfloat16*)symaddr(d_fcW_l);
    __nv_bfloat16* p_emb_h  = (__nv_bfloat16*)symaddr(d_embbf_h);
    __nv_bfloat16* p_emb_l  = (__nv_bfloat16*)symaddr(d_embbf_l);
    __nv_bfloat16* p_hbf_h  = (__nv_bfloat16*)symaddr(d_houtbf_h);
    __nv_bfloat16* p_hbf_l  = (__nv_bfloat16*)symaddr(d_houtbf_l);

    float* p_pre  = (float*)symaddr(d_pre);
    float* p_part = (float*)symaddr(d_part);
    float* p_c    = (float*)symaddr(d_c);
    float* p_P1   = (float*)symaddr(d_P1);
    float* p_P3   = (float*)symaddr(d_P3);

    // opt-in to >48KB dynamic smem (idempotent)
    cudaFuncAttributes fa;
    cudaFuncGetAttributes(&fa, mma_nt);
    if (fa.maxDynamicSharedSizeBytes < MMA_SMEM_BYTES)
        cudaFuncSetAttribute(mma_nt, cudaFuncAttributeMaxDynamicSharedMemorySize,
                             MMA_SMEM_BYTES);
    cudaFuncGetAttributes(&fa, init_mma);
    if (fa.maxDynamicSharedSizeBytes < INIT_SMEM_BYTES)
        cudaFuncSetAttribute(init_mma, cudaFuncAttributeMaxDynamicSharedMemorySize,
                             INIT_SMEM_BYTES);
    cudaFuncGetAttributes(&fa, small_mma);
    if (fa.maxDynamicSharedSizeBytes < SMALL_SMEM)
        cudaFuncSetAttribute(small_mma, cudaFuncAttributeMaxDynamicSharedMemorySize,
                             SMALL_SMEM);

    // side stream + events (host-side objects only)
    static cudaStream_t s2 = nullptr;
    static cudaEvent_t evA = nullptr, evB = nullptr;
    if (!s2) {
        cudaStreamCreateWithFlags(&s2, cudaStreamNonBlocking);
        cudaEventCreateWithFlags(&evA, cudaEventDisableTiming);
        cudaEventCreateWithFlags(&evB, cudaEventDisableTiming);
    }

    // ---- conversions: main on stream0 (critical), aux on s2 ----
    cvt_main<<<11008, 256>>>(features, W_ih, attn_feat_W);
    cudaEventRecord(evA, 0);

    // ---- fork: aux conversions + init GEMM chain on s2 ----
    cudaStreamWaitEvent(s2, evA, 0);
    cvt_aux<<<6304, 256, 0, s2>>>(fc_W, attn_token_W, W_hh);
    init_mma<<<dim3(8, NSPLIT), 256, INIT_SMEM_BYTES, s2>>>(init_Wh, init_Wc, p_part);
    reduce_init<<<256, 256, 0, s2>>>(p_part, p_c);
    cudaEventRecord(evB, s2);

    // ---- stream 0: remaining prologue ----
    emb_gather_bf<<<TSTEPS * NBATCH, 128>>>(captions, embd_W, p_emb_h, p_emb_l);
    // pre_emb = emb @ W_ih[:,1536:]^T  (2048 x 2048, K=512)
    mma_nt<<<dim3(32, 16, 1), 256, MMA_SMEM_BYTES>>>(
        p_emb_h, p_emb_l, EMBD, TSTEPS * NBATCH, p_Wih_h + 1536, p_Wih_l + 1536, G4,
        p_pre, G4, G4, 8, nullptr, 0, 0);
    // merged: attn_img (fp16) + G (fp16)
    mma_nt<<<dim3(40, 32, 1), 256, MMA_SMEM_BYTES>>>(
        p_feat_h, p_feat_l, ENCC, MROWS, p_afW_h, p_afW_l, ENCC,
        nullptr, ADIM, ADIM, 24, attn_feat_b, 3, 0);

    // ---- join: h0/c0 + aux conversions ready before the recurrence ----
    cudaStreamWaitEvent((cudaStream_t)0, evB, 0);

    // ---- sequential recurrence: 3 launches per step (final shape) ----
    for (int t = 0; t < TSTEPS; ++t) {
        small_mma<<<dim3(40, 4), 256, SMALL_SMEM>>>(p_P1, p_P3);
        attn_softmax<<<64, 512>>>(p_P1, attn_token_b, attn_full_W);
        gates_lstm<<<dim3(64, 8), 256>>>(p_P3, p_pre + (size_t)t * NBATCH * G4,
                                         b_ih, b_hh, t);
    }

    // ---- epilogue: FC over all timesteps (t-major rows, mode 5) ----
    mma_nt<<<dim3(157, 16, 1), 256, MMA_SMEM_BYTES>>>(
        p_hbf_h, p_hbf_l, HDIM, TSTEPS * NBATCH, p_fcW_h, p_fcW_l, HDIM,
        out, VOCAB, VOCAB, 8, fc_b, 5, 0);
}